// round 2
// baseline (speedup 1.0000x reference)
#include <cuda_runtime.h>
#include <math.h>

// Problem constants
#define PB 4
#define PS 2048
#define PD 1024
#define PH 16
#define PHD 64
#define PM (PB*PS)        // 8192 tokens

// Scratch (allocation-free rule: __device__ globals)
__device__ float g_Qh[PB*PH*PS*PHD];   // [B,H,S,HD]
__device__ float g_Kh[PB*PH*PS*PHD];
__device__ float g_Vh[PB*PH*PS*PHD];
__device__ float g_AO[PB*PS*PD];       // [B,S,D]

// ---------------------------------------------------------------------------
// Projection GEMM: out[M,N] = X[M,K] @ W[N,K]^T + bias
// BM=128, BN=64, BK=16, 256 threads, 8x4 per-thread tile.
// head_split=1: scatter n->(h,hd), m->(b,s) into [B,H,S,HD] layout.
// ---------------------------------------------------------------------------
__global__ __launch_bounds__(256) void proj_kernel(
    const float* __restrict__ X, const float* __restrict__ W,
    const float* __restrict__ bias, float* __restrict__ outp, int head_split)
{
    const int K = 1024;
    __shared__ float As[16][128];  // [k][m]
    __shared__ float Bs[16][64];   // [k][n]

    int tid = threadIdx.x;
    int m0 = blockIdx.y * 128;
    int n0 = blockIdx.x * 64;

    // global->smem mapping
    int arow = tid >> 1;            // 0..127
    int acol = (tid & 1) * 8;       // 0 or 8
    int brow = tid >> 2;            // 0..63
    int bcol = (tid & 3) * 4;       // 0,4,8,12

    int tidm = tid >> 4;            // 0..15
    int tidn = tid & 15;            // 0..15

    float acc[8][4];
#pragma unroll
    for (int i = 0; i < 8; i++)
#pragma unroll
        for (int j = 0; j < 4; j++) acc[i][j] = 0.f;

    const float* Xp = X + (m0 + arow) * K + acol;
    const float* Wp = W + (n0 + brow) * K + bcol;

    for (int k0 = 0; k0 < K; k0 += 16) {
        __syncthreads();
        float4 a0 = *(const float4*)(Xp + k0);
        float4 a1 = *(const float4*)(Xp + k0 + 4);
        float4 b0 = *(const float4*)(Wp + k0);
        As[acol + 0][arow] = a0.x; As[acol + 1][arow] = a0.y;
        As[acol + 2][arow] = a0.z; As[acol + 3][arow] = a0.w;
        As[acol + 4][arow] = a1.x; As[acol + 5][arow] = a1.y;
        As[acol + 6][arow] = a1.z; As[acol + 7][arow] = a1.w;
        Bs[bcol + 0][brow] = b0.x; Bs[bcol + 1][brow] = b0.y;
        Bs[bcol + 2][brow] = b0.z; Bs[bcol + 3][brow] = b0.w;
        __syncthreads();

#pragma unroll
        for (int kk = 0; kk < 16; kk++) {
            float4 av0 = *(const float4*)&As[kk][tidm * 8];
            float4 av1 = *(const float4*)&As[kk][tidm * 8 + 4];
            float4 bv  = *(const float4*)&Bs[kk][tidn * 4];
            float a[8] = {av0.x, av0.y, av0.z, av0.w, av1.x, av1.y, av1.z, av1.w};
            float bb[4] = {bv.x, bv.y, bv.z, bv.w};
#pragma unroll
            for (int i = 0; i < 8; i++)
#pragma unroll
                for (int j = 0; j < 4; j++)
                    acc[i][j] = fmaf(a[i], bb[j], acc[i][j]);
        }
    }

    int n = n0 + tidn * 4;
    float4 bia = *(const float4*)&bias[n];
    int m_base = m0 + tidm * 8;
#pragma unroll
    for (int i = 0; i < 8; i++) {
        int m = m_base + i;
        float4 c = make_float4(acc[i][0] + bia.x, acc[i][1] + bia.y,
                               acc[i][2] + bia.z, acc[i][3] + bia.w);
        if (head_split) {
            int bb_ = m >> 11;          // m / 2048
            int s   = m & 2047;
            int hh_ = n >> 6;           // n / 64
            int hd  = n & 63;
            *(float4*)&outp[(((bb_ * PH + hh_) * PS + s) << 6) + hd] = c;
        } else {
            *(float4*)&outp[m * 1024 + n] = c;
        }
    }
}

// ---------------------------------------------------------------------------
// Fused flash attention (fp32, online softmax).
// grid = (S/64, H, B), 256 threads. 64-query x 64-key tiles, HD=64.
// Thread grid 16x16, each thread owns a 4(q) x 4(j / d) tile.
// Qt/Kt stored d-major (transposed), Vs natural, Pt j-major padded to 68.
// ---------------------------------------------------------------------------
#define ATTN_SMEM_FLOATS (4096*3 + 64*68)

__global__ __launch_bounds__(256) void attn_kernel(
    const int* __restrict__ mask, float* __restrict__ AO)
{
    extern __shared__ float sm[];
    float* Qt = sm;              // [64][64] Qt[d][q]
    float* Kt = sm + 4096;       // [64][64] Kt[d][j]
    float* Vs = sm + 8192;       // [64][64] Vs[j][d]
    float* Pt = sm + 12288;      // [64][68] Pt[j][q]

    int tid = threadIdx.x;
    int q0 = blockIdx.x * 64;
    int h  = blockIdx.y;
    int b  = blockIdx.z;

    const float* Qb = g_Qh + ((b * PH + h) * PS) * PHD;
    const float* Kb = g_Kh + ((b * PH + h) * PS) * PHD;
    const float* Vb = g_Vh + ((b * PH + h) * PS) * PHD;

    int ld_row = tid >> 2;          // 0..63
    int ld_col = (tid & 3) * 16;    // 0,16,32,48

    // Load Q tile, transposed into Qt[d][q]
    {
        const float* src = Qb + (q0 + ld_row) * 64 + ld_col;
        float4 r0 = *(const float4*)(src);
        float4 r1 = *(const float4*)(src + 4);
        float4 r2 = *(const float4*)(src + 8);
        float4 r3 = *(const float4*)(src + 12);
        float rr[16] = {r0.x,r0.y,r0.z,r0.w, r1.x,r1.y,r1.z,r1.w,
                        r2.x,r2.y,r2.z,r2.w, r3.x,r3.y,r3.z,r3.w};
#pragma unroll
        for (int i = 0; i < 16; i++)
            Qt[(ld_col + i) * 64 + ld_row] = rr[i];
    }

    int tyq = tid >> 4;   // 0..15 -> q rows tyq*4..+3
    int txj = tid & 15;   // 0..15 -> j cols / d cols txj*4..+3

    float acc[4][4];
#pragma unroll
    for (int i = 0; i < 4; i++)
#pragma unroll
        for (int j = 0; j < 4; j++) acc[i][j] = 0.f;

    float rm[4], rl[4];
    bool valid[4];
#pragma unroll
    for (int qq = 0; qq < 4; qq++) {
        rm[qq] = -INFINITY;
        rl[qq] = 0.f;
        valid[qq] = (mask[b * PS + q0 + tyq * 4 + qq] != 0);
    }

    for (int j0 = 0; j0 < PS; j0 += 64) {
        __syncthreads();
        // Load K (transposed) and V (natural)
        {
            const float* ks = Kb + (j0 + ld_row) * 64 + ld_col;
            float4 k0 = *(const float4*)(ks);
            float4 k1 = *(const float4*)(ks + 4);
            float4 k2 = *(const float4*)(ks + 8);
            float4 k3 = *(const float4*)(ks + 12);
            float kr[16] = {k0.x,k0.y,k0.z,k0.w, k1.x,k1.y,k1.z,k1.w,
                            k2.x,k2.y,k2.z,k2.w, k3.x,k3.y,k3.z,k3.w};
#pragma unroll
            for (int i = 0; i < 16; i++)
                Kt[(ld_col + i) * 64 + ld_row] = kr[i];

            const float* vsrc = Vb + (j0 + ld_row) * 64 + ld_col;
#pragma unroll
            for (int i = 0; i < 4; i++)
                *(float4*)&Vs[ld_row * 64 + ld_col + i * 4] =
                    *(const float4*)(vsrc + i * 4);
        }
        __syncthreads();

        // Scores: s[qq][jj] = sum_d Q[q][d] * K[j][d]
        float s[4][4];
#pragma unroll
        for (int i = 0; i < 4; i++)
#pragma unroll
            for (int j = 0; j < 4; j++) s[i][j] = 0.f;

#pragma unroll 4
        for (int d = 0; d < 64; d++) {
            float4 qv = *(const float4*)&Qt[(d << 6) + (tyq << 2)];
            float4 kv = *(const float4*)&Kt[(d << 6) + (txj << 2)];
            float qa[4] = {qv.x, qv.y, qv.z, qv.w};
            float ka[4] = {kv.x, kv.y, kv.z, kv.w};
#pragma unroll
            for (int i = 0; i < 4; i++)
#pragma unroll
                for (int j = 0; j < 4; j++)
                    s[i][j] = fmaf(qa[i], ka[j], s[i][j]);
        }

        // scale + query-row mask
#pragma unroll
        for (int qq = 0; qq < 4; qq++)
#pragma unroll
            for (int jj = 0; jj < 4; jj++)
                s[qq][jj] = valid[qq] ? s[qq][jj] * 0.125f : -1e9f;

        // online softmax per q row (replicated consistently across 16 txj lanes)
        float p[4][4];
#pragma unroll
        for (int qq = 0; qq < 4; qq++) {
            float tm = fmaxf(fmaxf(s[qq][0], s[qq][1]), fmaxf(s[qq][2], s[qq][3]));
#pragma unroll
            for (int off = 8; off >= 1; off >>= 1)
                tm = fmaxf(tm, __shfl_xor_sync(0xffffffffu, tm, off));
            float mnew = fmaxf(rm[qq], tm);
            float corr = __expf(rm[qq] - mnew);
            rm[qq] = mnew;
            float ls = 0.f;
#pragma unroll
            for (int jj = 0; jj < 4; jj++) {
                p[qq][jj] = __expf(s[qq][jj] - mnew);
                ls += p[qq][jj];
            }
#pragma unroll
            for (int off = 8; off >= 1; off >>= 1)
                ls += __shfl_xor_sync(0xffffffffu, ls, off);
            rl[qq] = rl[qq] * corr + ls;
#pragma unroll
            for (int dd = 0; dd < 4; dd++) acc[qq][dd] *= corr;
        }

        __syncthreads();   // previous-iteration Pt readers are done (loop-top sync)
#pragma unroll
        for (int jj = 0; jj < 4; jj++)
#pragma unroll
            for (int qq = 0; qq < 4; qq++)
                Pt[(txj * 4 + jj) * 68 + tyq * 4 + qq] = p[qq][jj];
        __syncthreads();

        // PV: acc[qq][dd] += sum_j P[q][j] * V[j][d]
#pragma unroll 4
        for (int j = 0; j < 64; j++) {
            float4 pv = *(const float4*)&Pt[j * 68 + (tyq << 2)];
            float4 vv = *(const float4*)&Vs[(j << 6) + (txj << 2)];
            float pa[4] = {pv.x, pv.y, pv.z, pv.w};
            float va[4] = {vv.x, vv.y, vv.z, vv.w};
#pragma unroll
            for (int qq = 0; qq < 4; qq++)
#pragma unroll
                for (int dd = 0; dd < 4; dd++)
                    acc[qq][dd] = fmaf(pa[qq], va[dd], acc[qq][dd]);
        }
    }

    // Write merged-head output [B,S,D]
#pragma unroll
    for (int qq = 0; qq < 4; qq++) {
        float inv = 1.f / rl[qq];
        int q = q0 + tyq * 4 + qq;
        float4 o = make_float4(acc[qq][0] * inv, acc[qq][1] * inv,
                               acc[qq][2] * inv, acc[qq][3] * inv);
        *(float4*)&AO[(b * PS + q) * PD + h * 64 + txj * 4] = o;
    }
}

// ---------------------------------------------------------------------------
extern "C" void kernel_launch(void* const* d_in, const int* in_sizes, int n_in,
                              void* d_out, int out_size)
{
    const float* q   = (const float*)d_in[0];
    const float* k   = (const float*)d_in[1];
    const float* v   = (const float*)d_in[2];
    const float* Wq  = (const float*)d_in[3];
    const float* bq  = (const float*)d_in[4];
    const float* Wk  = (const float*)d_in[5];
    const float* bk  = (const float*)d_in[6];
    const float* Wv  = (const float*)d_in[7];
    const float* bv  = (const float*)d_in[8];
    const float* Wo  = (const float*)d_in[9];
    const float* bo  = (const float*)d_in[10];
    const int*   msk = (const int*)d_in[11];
    float* out = (float*)d_out;

    float *qh, *kh, *vh, *ao;
    cudaGetSymbolAddress((void**)&qh, g_Qh);
    cudaGetSymbolAddress((void**)&kh, g_Kh);
    cudaGetSymbolAddress((void**)&vh, g_Vh);
    cudaGetSymbolAddress((void**)&ao, g_AO);

    dim3 pgrid(PD / 64, PM / 128);   // (16, 64)
    dim3 pblk(256);

    proj_kernel<<<pgrid, pblk>>>(q, Wq, bq, qh, 1);
    proj_kernel<<<pgrid, pblk>>>(k, Wk, bk, kh, 1);
    proj_kernel<<<pgrid, pblk>>>(v, Wv, bv, vh, 1);

    size_t attn_smem = ATTN_SMEM_FLOATS * sizeof(float);   // 66560 B
    cudaFuncSetAttribute(attn_kernel,
                         cudaFuncAttributeMaxDynamicSharedMemorySize,
                         (int)attn_smem);
    attn_kernel<<<dim3(PS / 64, PH, PB), 256, attn_smem>>>(msk, ao);

    proj_kernel<<<pgrid, pblk>>>(ao, Wo, bo, out, 0);
}

// round 4
// speedup vs baseline: 1.8759x; 1.8759x over previous
#include <cuda_runtime.h>
#include <math.h>
#include <stdint.h>

// Problem constants
#define PB 4
#define PS 2048
#define PD 1024
#define PH 16
#define PHD 64
#define PM (PB*PS)        // 8192 tokens
#define AP 68             // attention smem pitch (floats)

// Scratch (allocation-free rule: __device__ globals)
__device__ float g_Qh[PB*PH*PS*PHD];   // [B,H,S,HD]
__device__ float g_Kh[PB*PH*PS*PHD];
__device__ float g_Vh[PB*PH*PS*PHD];
__device__ float g_AO[PB*PS*PD];       // [B,S,D]

// ---------------------------------------------------------------------------
// Helpers
// ---------------------------------------------------------------------------
__device__ __forceinline__ float f2tf32f(float x) {
    uint32_t r;
    asm("cvt.rna.tf32.f32 %0, %1;" : "=r"(r) : "f"(x));
    return __uint_as_float(r);
}

__device__ __forceinline__ void mma_tf32(float c[4],
    uint32_t a0, uint32_t a1, uint32_t a2, uint32_t a3,
    uint32_t b0, uint32_t b1)
{
    asm volatile(
        "mma.sync.aligned.m16n8k8.row.col.f32.tf32.tf32.f32 "
        "{%0,%1,%2,%3}, {%4,%5,%6,%7}, {%8,%9}, {%0,%1,%2,%3};"
        : "+f"(c[0]), "+f"(c[1]), "+f"(c[2]), "+f"(c[3])
        : "r"(a0), "r"(a1), "r"(a2), "r"(a3), "r"(b0), "r"(b1));
}

// ---------------------------------------------------------------------------
// Projection GEMM on tensor cores (3xTF32): out[M,N] = X[M,K] @ W[N,K]^T + b
// BM=128, BN=128, BK=16. 256 threads = 8 warps, warp tile 64x32.
// smem tiles padded to 20 floats/row -> conflict-free fragment LDS.
// ---------------------------------------------------------------------------
__global__ __launch_bounds__(256) void proj_tc_kernel(
    const float* __restrict__ X, const float* __restrict__ W,
    const float* __restrict__ bias, float* __restrict__ outp, int head_split)
{
    __shared__ float Xh[128*20], Xl[128*20], Wh[128*20], Wl[128*20];

    int tid  = threadIdx.x;
    int lane = tid & 31, warp = tid >> 5;
    int g = lane >> 2, t = lane & 3;
    int m0 = blockIdx.y * 128, n0 = blockIdx.x * 128;
    int wm0 = (warp >> 2) * 64;     // 0 or 64
    int wn0 = (warp & 3) * 32;      // 0,32,64,96

    // gmem staging: each thread owns 8 consecutive k of one row
    int lrow = tid >> 1;            // 0..127
    int lkc  = (tid & 1) * 8;       // 0 or 8
    const float* Xg = X + (m0 + lrow) * 1024 + lkc;
    const float* Wg = W + (n0 + lrow) * 1024 + lkc;
    int sbase = lrow * 20 + lkc;

    int abase = (wm0 + g) * 20 + t;
    int bbase = (wn0 + g) * 20 + t;

    float c[4][4][4];
#pragma unroll
    for (int mt = 0; mt < 4; mt++)
#pragma unroll
        for (int nt = 0; nt < 4; nt++)
#pragma unroll
            for (int i = 0; i < 4; i++) c[mt][nt][i] = 0.f;

    float4 xr0 = *(const float4*)(Xg);
    float4 xr1 = *(const float4*)(Xg + 4);
    float4 wr0 = *(const float4*)(Wg);
    float4 wr1 = *(const float4*)(Wg + 4);

    for (int k0 = 0; k0 < 1024; k0 += 16) {
        __syncthreads();   // previous iteration's fragment reads done

        // split into tf32 hi/lo and store to smem (vectorized)
        {
            float xv[8] = {xr0.x, xr0.y, xr0.z, xr0.w, xr1.x, xr1.y, xr1.z, xr1.w};
            float wv[8] = {wr0.x, wr0.y, wr0.z, wr0.w, wr1.x, wr1.y, wr1.z, wr1.w};
            float xh[8], xl[8], wh[8], wl[8];
#pragma unroll
            for (int i = 0; i < 8; i++) {
                xh[i] = f2tf32f(xv[i]); xl[i] = f2tf32f(xv[i] - xh[i]);
                wh[i] = f2tf32f(wv[i]); wl[i] = f2tf32f(wv[i] - wh[i]);
            }
            *(float4*)&Xh[sbase]     = make_float4(xh[0], xh[1], xh[2], xh[3]);
            *(float4*)&Xh[sbase + 4] = make_float4(xh[4], xh[5], xh[6], xh[7]);
            *(float4*)&Xl[sbase]     = make_float4(xl[0], xl[1], xl[2], xl[3]);
            *(float4*)&Xl[sbase + 4] = make_float4(xl[4], xl[5], xl[6], xl[7]);
            *(float4*)&Wh[sbase]     = make_float4(wh[0], wh[1], wh[2], wh[3]);
            *(float4*)&Wh[sbase + 4] = make_float4(wh[4], wh[5], wh[6], wh[7]);
            *(float4*)&Wl[sbase]     = make_float4(wl[0], wl[1], wl[2], wl[3]);
            *(float4*)&Wl[sbase + 4] = make_float4(wl[4], wl[5], wl[6], wl[7]);
        }
        __syncthreads();

        // prefetch next K tile
        if (k0 + 16 < 1024) {
            xr0 = *(const float4*)(Xg + k0 + 16);
            xr1 = *(const float4*)(Xg + k0 + 20);
            wr0 = *(const float4*)(Wg + k0 + 16);
            wr1 = *(const float4*)(Wg + k0 + 20);
        }

#pragma unroll
        for (int kb = 0; kb < 16; kb += 8) {
            uint32_t ah[4][4], al[4][4];
#pragma unroll
            for (int mt = 0; mt < 4; mt++) {
                int base = abase + mt * 320 + kb;
                ah[mt][0] = __float_as_uint(Xh[base]);
                ah[mt][1] = __float_as_uint(Xh[base + 160]);
                ah[mt][2] = __float_as_uint(Xh[base + 4]);
                ah[mt][3] = __float_as_uint(Xh[base + 164]);
                al[mt][0] = __float_as_uint(Xl[base]);
                al[mt][1] = __float_as_uint(Xl[base + 160]);
                al[mt][2] = __float_as_uint(Xl[base + 4]);
                al[mt][3] = __float_as_uint(Xl[base + 164]);
            }
            uint32_t bh[4][2], bl[4][2];
#pragma unroll
            for (int nt = 0; nt < 4; nt++) {
                int base = bbase + nt * 160 + kb;
                bh[nt][0] = __float_as_uint(Wh[base]);
                bh[nt][1] = __float_as_uint(Wh[base + 4]);
                bl[nt][0] = __float_as_uint(Wl[base]);
                bl[nt][1] = __float_as_uint(Wl[base + 4]);
            }
#pragma unroll
            for (int mt = 0; mt < 4; mt++)
#pragma unroll
                for (int nt = 0; nt < 4; nt++) {
                    mma_tf32(c[mt][nt], ah[mt][0], ah[mt][1], ah[mt][2], ah[mt][3],
                             bh[nt][0], bh[nt][1]);
                    mma_tf32(c[mt][nt], ah[mt][0], ah[mt][1], ah[mt][2], ah[mt][3],
                             bl[nt][0], bl[nt][1]);
                    mma_tf32(c[mt][nt], al[mt][0], al[mt][1], al[mt][2], al[mt][3],
                             bh[nt][0], bh[nt][1]);
                }
        }
    }

    // epilogue: bias + store (float2 per row-half)
#pragma unroll
    for (int nt = 0; nt < 4; nt++) {
        int n = n0 + wn0 + nt * 8 + 2 * t;
        float b0v = bias[n], b1v = bias[n + 1];
#pragma unroll
        for (int mt = 0; mt < 4; mt++) {
            int r0 = m0 + wm0 + mt * 16 + g;
            int r1 = r0 + 8;
            float2 v0 = make_float2(c[mt][nt][0] + b0v, c[mt][nt][1] + b1v);
            float2 v1 = make_float2(c[mt][nt][2] + b0v, c[mt][nt][3] + b1v);
            if (head_split) {
                int hh = n >> 6, hd = n & 63;
                int bb0 = r0 >> 11, s0 = r0 & 2047;
                int bb1 = r1 >> 11, s1 = r1 & 2047;
                *(float2*)&outp[(((bb0 * PH + hh) * PS + s0) << 6) + hd] = v0;
                *(float2*)&outp[(((bb1 * PH + hh) * PS + s1) << 6) + hd] = v1;
            } else {
                *(float2*)&outp[r0 * PD + n] = v0;
                *(float2*)&outp[r1 * PD + n] = v1;
            }
        }
    }
}

// ---------------------------------------------------------------------------
// Tensor-core flash attention (tf32 single-pass MMAs, fp32 softmax).
// grid = (S/128, H, B), 256 threads = 8 warps. CTA tile: 128 q x 64 keys.
// Warp w owns q rows [w*16, w*16+16) for ALL keys (no cross-warp reductions).
// smem: Qs[128][AP], Ks[64][AP], Vt[64][AP] (d-major), Ps[128][AP]. AP=68
// gives conflict-free (4g+t) fragment addressing.
// ---------------------------------------------------------------------------
#define ATTN_SMEM_BYTES ((128 + 64 + 64 + 128) * AP * 4)

__global__ __launch_bounds__(256) void attn_tc_kernel(
    const int* __restrict__ mask, float* __restrict__ AO)
{
    extern __shared__ float sm[];
    float* Qs = sm;                   // [128][AP]
    float* Ks = Qs + 128 * AP;        // [64][AP]
    float* Vt = Ks + 64 * AP;         // [64][AP], Vt[d][j]
    float* Ps = Vt + 64 * AP;         // [128][AP]

    int tid  = threadIdx.x;
    int lane = tid & 31, warp = tid >> 5;
    int g = lane >> 2, t = lane & 3;
    int q0 = blockIdx.x * 128;
    int h  = blockIdx.y;
    int b  = blockIdx.z;

    const float* Qb = g_Qh + (size_t)((b * PH + h) * PS) * PHD;
    const float* Kb = g_Kh + (size_t)((b * PH + h) * PS) * PHD;
    const float* Vb = g_Vh + (size_t)((b * PH + h) * PS) * PHD;

    // stage Q (tf32-rounded): thread row = tid/2, half-row = 32 floats
    {
        int row = tid >> 1, c0 = (tid & 1) * 32;
        const float* src = Qb + (q0 + row) * 64 + c0;
        float* dst = Qs + row * AP + c0;
#pragma unroll
        for (int i = 0; i < 8; i++) {
            float4 v = *(const float4*)(src + i * 4);
            v.x = f2tf32f(v.x); v.y = f2tf32f(v.y);
            v.z = f2tf32f(v.z); v.w = f2tf32f(v.w);
            *(float4*)(dst + i * 4) = v;
        }
    }

    int qrow = warp * 16 + g;   // low fragment row within CTA tile
    bool v0 = mask[b * PS + q0 + qrow] != 0;
    bool v1 = mask[b * PS + q0 + qrow + 8] != 0;

    float m0 = -INFINITY, m1 = -INFINITY, l0 = 0.f, l1 = 0.f;
    float o[8][4];
#pragma unroll
    for (int nt = 0; nt < 8; nt++)
#pragma unroll
        for (int i = 0; i < 4; i++) o[nt][i] = 0.f;

    int krow  = tid >> 2;          // 0..63 (K/V staging row = key index)
    int kcol  = (tid & 3) * 16;    // K staging col base
    int dbase = (tid & 3) * 4;     // V transpose d base (interleaved)

    for (int j0 = 0; j0 < PS; j0 += 64) {
        __syncthreads();   // prior tile's Ks/Vt reads complete
        {
            const float* ks = Kb + (j0 + krow) * 64 + kcol;
            float* kd = Ks + krow * AP + kcol;
#pragma unroll
            for (int i = 0; i < 4; i++) {
                float4 v = *(const float4*)(ks + i * 4);
                v.x = f2tf32f(v.x); v.y = f2tf32f(v.y);
                v.z = f2tf32f(v.z); v.w = f2tf32f(v.w);
                *(float4*)(kd + i * 4) = v;
            }
            const float* vs = Vb + (j0 + krow) * 64;
#pragma unroll
            for (int kk = 0; kk < 4; kk++) {
                float4 v = *(const float4*)(vs + dbase + kk * 16);
                int d = dbase + kk * 16;
                Vt[(d + 0) * AP + krow] = f2tf32f(v.x);
                Vt[(d + 1) * AP + krow] = f2tf32f(v.y);
                Vt[(d + 2) * AP + krow] = f2tf32f(v.z);
                Vt[(d + 3) * AP + krow] = f2tf32f(v.w);
            }
        }
        __syncthreads();

        // S = Q K^T  (s[nt]: rows qrow/qrow+8, cols nt*8+2t, +1)
        float s[8][4];
#pragma unroll
        for (int nt = 0; nt < 8; nt++)
#pragma unroll
            for (int i = 0; i < 4; i++) s[nt][i] = 0.f;

#pragma unroll
        for (int kc = 0; kc < 8; kc++) {
            int qb_ = qrow * AP + kc * 8 + t;
            uint32_t a0 = __float_as_uint(Qs[qb_]);
            uint32_t a1 = __float_as_uint(Qs[qb_ + 8 * AP]);
            uint32_t a2 = __float_as_uint(Qs[qb_ + 4]);
            uint32_t a3 = __float_as_uint(Qs[qb_ + 8 * AP + 4]);
#pragma unroll
            for (int nt = 0; nt < 8; nt++) {
                int bb_ = (nt * 8 + g) * AP + kc * 8 + t;
                uint32_t b0 = __float_as_uint(Ks[bb_]);
                uint32_t b1 = __float_as_uint(Ks[bb_ + 4]);
                mma_tf32(s[nt], a0, a1, a2, a3, b0, b1);
            }
        }

        // scale + query-row mask
#pragma unroll
        for (int nt = 0; nt < 8; nt++) {
            s[nt][0] = v0 ? s[nt][0] * 0.125f : -1e9f;
            s[nt][1] = v0 ? s[nt][1] * 0.125f : -1e9f;
            s[nt][2] = v1 ? s[nt][2] * 0.125f : -1e9f;
            s[nt][3] = v1 ? s[nt][3] * 0.125f : -1e9f;
        }

        // tile row maxes (reduce across the 4 t-lanes of each row)
        float tm0 = -INFINITY, tm1 = -INFINITY;
#pragma unroll
        for (int nt = 0; nt < 8; nt++) {
            tm0 = fmaxf(tm0, fmaxf(s[nt][0], s[nt][1]));
            tm1 = fmaxf(tm1, fmaxf(s[nt][2], s[nt][3]));
        }
        tm0 = fmaxf(tm0, __shfl_xor_sync(0xffffffffu, tm0, 1));
        tm0 = fmaxf(tm0, __shfl_xor_sync(0xffffffffu, tm0, 2));
        tm1 = fmaxf(tm1, __shfl_xor_sync(0xffffffffu, tm1, 1));
        tm1 = fmaxf(tm1, __shfl_xor_sync(0xffffffffu, tm1, 2));

        // online update
        float mn0 = fmaxf(m0, tm0), mn1 = fmaxf(m1, tm1);
        float cr0 = __expf(m0 - mn0), cr1 = __expf(m1 - mn1);
        m0 = mn0; m1 = mn1;
        l0 *= cr0; l1 *= cr1;
#pragma unroll
        for (int nt = 0; nt < 8; nt++) {
            o[nt][0] *= cr0; o[nt][1] *= cr0;
            o[nt][2] *= cr1; o[nt][3] *= cr1;
        }

        // probabilities (tf32-rounded; same values feed l and PV)
#pragma unroll
        for (int nt = 0; nt < 8; nt++) {
            float p0 = f2tf32f(__expf(s[nt][0] - m0));
            float p1 = f2tf32f(__expf(s[nt][1] - m0));
            float p2 = f2tf32f(__expf(s[nt][2] - m1));
            float p3 = f2tf32f(__expf(s[nt][3] - m1));
            l0 += p0 + p1;
            l1 += p2 + p3;
            int col = nt * 8 + 2 * t;
            Ps[qrow * AP + col]           = p0;
            Ps[qrow * AP + col + 1]       = p1;
            Ps[(qrow + 8) * AP + col]     = p2;
            Ps[(qrow + 8) * AP + col + 1] = p3;
        }
        __syncwarp();   // P rows are warp-private; order STS -> LDS in-warp

        // O += P V   (A = Ps rows, B = Vt[d][j])
#pragma unroll
        for (int kc = 0; kc < 8; kc++) {
            int pb_ = qrow * AP + kc * 8 + t;
            uint32_t a0 = __float_as_uint(Ps[pb_]);
            uint32_t a1 = __float_as_uint(Ps[pb_ + 8 * AP]);
            uint32_t a2 = __float_as_uint(Ps[pb_ + 4]);
            uint32_t a3 = __float_as_uint(Ps[pb_ + 8 * AP + 4]);
#pragma unroll
            for (int nt = 0; nt < 8; nt++) {
                int bb_ = (nt * 8 + g) * AP + kc * 8 + t;
                uint32_t b0 = __float_as_uint(Vt[bb_]);
                uint32_t b1 = __float_as_uint(Vt[bb_ + 4]);
                mma_tf32(o[nt], a0, a1, a2, a3, b0, b1);
            }
        }
        __syncwarp();   // PV reads done before next tile's P stores
    }

    // final row sums (across the 4 t-lanes) and output
    l0 += __shfl_xor_sync(0xffffffffu, l0, 1);
    l0 += __shfl_xor_sync(0xffffffffu, l0, 2);
    l1 += __shfl_xor_sync(0xffffffffu, l1, 1);
    l1 += __shfl_xor_sync(0xffffffffu, l1, 2);
    float inv0 = 1.f / l0, inv1 = 1.f / l1;

    float* out0 = AO + (size_t)(b * PS + q0 + qrow) * PD + h * 64;
    float* out1 = out0 + (size_t)8 * PD;
#pragma unroll
    for (int nt = 0; nt < 8; nt++) {
        int d = nt * 8 + 2 * t;
        *(float2*)(out0 + d) = make_float2(o[nt][0] * inv0, o[nt][1] * inv0);
        *(float2*)(out1 + d) = make_float2(o[nt][2] * inv1, o[nt][3] * inv1);
    }
}

// ---------------------------------------------------------------------------
extern "C" void kernel_launch(void* const* d_in, const int* in_sizes, int n_in,
                              void* d_out, int out_size)
{
    const float* q   = (const float*)d_in[0];
    const float* k   = (const float*)d_in[1];
    const float* v   = (const float*)d_in[2];
    const float* Wq  = (const float*)d_in[3];
    const float* bq  = (const float*)d_in[4];
    const float* Wk  = (const float*)d_in[5];
    const float* bk  = (const float*)d_in[6];
    const float* Wv  = (const float*)d_in[7];
    const float* bv  = (const float*)d_in[8];
    const float* Wo  = (const float*)d_in[9];
    const float* bo  = (const float*)d_in[10];
    const int*   msk = (const int*)d_in[11];
    float* out = (float*)d_out;

    float *qh, *kh, *vh, *ao;
    cudaGetSymbolAddress((void**)&qh, g_Qh);
    cudaGetSymbolAddress((void**)&kh, g_Kh);
    cudaGetSymbolAddress((void**)&vh, g_Vh);
    cudaGetSymbolAddress((void**)&ao, g_AO);

    dim3 pgrid(PD / 128, PM / 128);   // (8, 64)
    dim3 pblk(256);

    proj_tc_kernel<<<pgrid, pblk>>>(q, Wq, bq, qh, 1);
    proj_tc_kernel<<<pgrid, pblk>>>(k, Wk, bk, kh, 1);
    proj_tc_kernel<<<pgrid, pblk>>>(v, Wv, bv, vh, 1);

    cudaFuncSetAttribute(attn_tc_kernel,
                         cudaFuncAttributeMaxDynamicSharedMemorySize,
                         ATTN_SMEM_BYTES);
    attn_tc_kernel<<<dim3(PS / 128, PH, PB), 256, ATTN_SMEM_BYTES>>>(msk, ao);

    proj_tc_kernel<<<pgrid, pblk>>>(ao, Wo, bo, out, 0);
}

// round 6
// speedup vs baseline: 2.2430x; 1.1957x over previous
#include <cuda_runtime.h>
#include <cuda_bf16.h>
#include <math.h>
#include <stdint.h>

// Problem constants
#define PB 4
#define PS 2048
#define PD 1024
#define PH 16
#define PHD 64
#define PM (PB*PS)        // 8192 tokens
#define AP 68             // attention smem pitch (floats)

// Scratch (allocation-free rule: __device__ globals)
__device__ float g_Qh[PB*PH*PS*PHD];   // [B,H,S,HD]
__device__ float g_Kh[PB*PH*PS*PHD];
__device__ float g_Vh[PB*PH*PS*PHD];
__device__ float g_AO[PB*PS*PD];       // [B,S,D]

// ---------------------------------------------------------------------------
// Helpers
// ---------------------------------------------------------------------------
__device__ __forceinline__ float f2tf32f(float x) {
    uint32_t r;
    asm("cvt.rna.tf32.f32 %0, %1;" : "=r"(r) : "f"(x));
    return __uint_as_float(r);
}

__device__ __forceinline__ void mma_tf32(float c[4],
    uint32_t a0, uint32_t a1, uint32_t a2, uint32_t a3,
    uint32_t b0, uint32_t b1)
{
    asm volatile(
        "mma.sync.aligned.m16n8k8.row.col.f32.tf32.tf32.f32 "
        "{%0,%1,%2,%3}, {%4,%5,%6,%7}, {%8,%9}, {%0,%1,%2,%3};"
        : "+f"(c[0]), "+f"(c[1]), "+f"(c[2]), "+f"(c[3])
        : "r"(a0), "r"(a1), "r"(a2), "r"(a3), "r"(b0), "r"(b1));
}

__device__ __forceinline__ void mma_bf16(float c[4],
    uint32_t a0, uint32_t a1, uint32_t a2, uint32_t a3,
    uint32_t b0, uint32_t b1)
{
    asm volatile(
        "mma.sync.aligned.m16n8k16.row.col.f32.bf16.bf16.f32 "
        "{%0,%1,%2,%3}, {%4,%5,%6,%7}, {%8,%9}, {%0,%1,%2,%3};"
        : "+f"(c[0]), "+f"(c[1]), "+f"(c[2]), "+f"(c[3])
        : "r"(a0), "r"(a1), "r"(a2), "r"(a3), "r"(b0), "r"(b1));
}

// split two floats into packed bf16x2 hi and lo words
__device__ __forceinline__ void split2(float x, float y,
                                       uint32_t& hi, uint32_t& lo)
{
    __nv_bfloat16 xh = __float2bfloat16_rn(x);
    __nv_bfloat16 yh = __float2bfloat16_rn(y);
    float xr = x - __bfloat162float(xh);
    float yr = y - __bfloat162float(yh);
    __nv_bfloat162 h = __halves2bfloat162(xh, yh);
    __nv_bfloat162 l = __floats2bfloat162_rn(xr, yr);
    hi = *reinterpret_cast<uint32_t*>(&h);
    lo = *reinterpret_cast<uint32_t*>(&l);
}

// ---------------------------------------------------------------------------
// Projection GEMM on tensor cores (3-term bf16 split, m16n8k16):
//   out[M,N] = X[M,K] @ W[N,K]^T + bias,  X*W ~= Xh*Wh + Xh*Wl + Xl*Wh
// BM=128, BN=128, BK=32. 256 threads = 8 warps, warp tile 64x32.
// smem: packed bf16x2 words, row pitch 20 (16 used) -> conflict-free frags.
// ---------------------------------------------------------------------------
__global__ __launch_bounds__(256) void proj_tc_kernel(
    const float* __restrict__ X, const float* __restrict__ W,
    const float* __restrict__ bias, float* __restrict__ outp, int head_split)
{
    __shared__ uint32_t Xh[128*20], Xl[128*20], Wh[128*20], Wl[128*20];

    int tid  = threadIdx.x;
    int lane = tid & 31, warp = tid >> 5;
    int g = lane >> 2, t = lane & 3;
    int m0 = blockIdx.y * 128, n0 = blockIdx.x * 128;
    int wm0 = (warp >> 2) * 64;     // 0 or 64
    int wn0 = (warp & 3) * 32;      // 0,32,64,96

    // gmem staging: each thread owns 16 consecutive k of one row
    int lrow = tid >> 1;            // 0..127
    int lkc  = (tid & 1) * 16;      // 0 or 16
    const float* Xg = X + (m0 + lrow) * 1024 + lkc;
    const float* Wg = W + (n0 + lrow) * 1024 + lkc;
    int sbase = lrow * 20 + (lkc >> 1);   // uint col = k/2

    float c[4][4][4];
#pragma unroll
    for (int mt = 0; mt < 4; mt++)
#pragma unroll
        for (int nt = 0; nt < 4; nt++)
#pragma unroll
            for (int i = 0; i < 4; i++) c[mt][nt][i] = 0.f;

    float4 xr[4], wr[4];
#pragma unroll
    for (int i = 0; i < 4; i++) {
        xr[i] = *(const float4*)(Xg + i * 4);
        wr[i] = *(const float4*)(Wg + i * 4);
    }

    for (int k0 = 0; k0 < 1024; k0 += 32) {
        __syncthreads();   // previous iteration's fragment reads done

        // split into bf16 hi/lo pairs and store packed to smem
        {
            uint32_t xh[8], xl[8], wh[8], wl[8];
#pragma unroll
            for (int i = 0; i < 4; i++) {
                split2(xr[i].x, xr[i].y, xh[2*i],   xl[2*i]);
                split2(xr[i].z, xr[i].w, xh[2*i+1], xl[2*i+1]);
                split2(wr[i].x, wr[i].y, wh[2*i],   wl[2*i]);
                split2(wr[i].z, wr[i].w, wh[2*i+1], wl[2*i+1]);
            }
            *(uint4*)&Xh[sbase]     = make_uint4(xh[0], xh[1], xh[2], xh[3]);
            *(uint4*)&Xh[sbase + 4] = make_uint4(xh[4], xh[5], xh[6], xh[7]);
            *(uint4*)&Xl[sbase]     = make_uint4(xl[0], xl[1], xl[2], xl[3]);
            *(uint4*)&Xl[sbase + 4] = make_uint4(xl[4], xl[5], xl[6], xl[7]);
            *(uint4*)&Wh[sbase]     = make_uint4(wh[0], wh[1], wh[2], wh[3]);
            *(uint4*)&Wh[sbase + 4] = make_uint4(wh[4], wh[5], wh[6], wh[7]);
            *(uint4*)&Wl[sbase]     = make_uint4(wl[0], wl[1], wl[2], wl[3]);
            *(uint4*)&Wl[sbase + 4] = make_uint4(wl[4], wl[5], wl[6], wl[7]);
        }
        __syncthreads();

        // prefetch next K tile
        if (k0 + 32 < 1024) {
#pragma unroll
            for (int i = 0; i < 4; i++) {
                xr[i] = *(const float4*)(Xg + k0 + 32 + i * 4);
                wr[i] = *(const float4*)(Wg + k0 + 32 + i * 4);
            }
        }

#pragma unroll
        for (int kc2 = 0; kc2 < 16; kc2 += 8) {   // two k16 chunks
            uint32_t ah[4][4], al[4][4];
#pragma unroll
            for (int mt = 0; mt < 4; mt++) {
                int base = (wm0 + g + mt * 16) * 20 + kc2 + t;
                ah[mt][0] = Xh[base];
                ah[mt][1] = Xh[base + 160];      // row + 8
                ah[mt][2] = Xh[base + 4];
                ah[mt][3] = Xh[base + 164];
                al[mt][0] = Xl[base];
                al[mt][1] = Xl[base + 160];
                al[mt][2] = Xl[base + 4];
                al[mt][3] = Xl[base + 164];
            }
            uint32_t bh[4][2], bl[4][2];
#pragma unroll
            for (int nt = 0; nt < 4; nt++) {
                int base = (wn0 + nt * 8 + g) * 20 + kc2 + t;
                bh[nt][0] = Wh[base];
                bh[nt][1] = Wh[base + 4];
                bl[nt][0] = Wl[base];
                bl[nt][1] = Wl[base + 4];
            }
#pragma unroll
            for (int mt = 0; mt < 4; mt++)
#pragma unroll
                for (int nt = 0; nt < 4; nt++) {
                    mma_bf16(c[mt][nt], ah[mt][0], ah[mt][1], ah[mt][2], ah[mt][3],
                             bh[nt][0], bh[nt][1]);
                    mma_bf16(c[mt][nt], ah[mt][0], ah[mt][1], ah[mt][2], ah[mt][3],
                             bl[nt][0], bl[nt][1]);
                    mma_bf16(c[mt][nt], al[mt][0], al[mt][1], al[mt][2], al[mt][3],
                             bh[nt][0], bh[nt][1]);
                }
        }
    }

    // epilogue: bias + store (float2 per row-half)
#pragma unroll
    for (int nt = 0; nt < 4; nt++) {
        int n = n0 + wn0 + nt * 8 + 2 * t;
        float b0v = bias[n], b1v = bias[n + 1];
#pragma unroll
        for (int mt = 0; mt < 4; mt++) {
            int r0 = m0 + wm0 + mt * 16 + g;
            int r1 = r0 + 8;
            float2 v0 = make_float2(c[mt][nt][0] + b0v, c[mt][nt][1] + b1v);
            float2 v1 = make_float2(c[mt][nt][2] + b0v, c[mt][nt][3] + b1v);
            if (head_split) {
                int hh = n >> 6, hd = n & 63;
                int bb0 = r0 >> 11, s0 = r0 & 2047;
                int bb1 = r1 >> 11, s1 = r1 & 2047;
                *(float2*)&outp[(((bb0 * PH + hh) * PS + s0) << 6) + hd] = v0;
                *(float2*)&outp[(((bb1 * PH + hh) * PS + s1) << 6) + hd] = v1;
            } else {
                *(float2*)&outp[r0 * PD + n] = v0;
                *(float2*)&outp[r1 * PD + n] = v1;
            }
        }
    }
}

// ---------------------------------------------------------------------------
// Tensor-core flash attention (tf32 single-pass MMAs, fp32 softmax).
// grid = (S/128, H, B), 256 threads = 8 warps. CTA tile: 128 q x 64 keys.
// Warp w owns q rows [w*16, w*16+16) for ALL keys (no cross-warp reductions).
// smem: Qs[128][AP], Ks[64][AP], Vt[64][AP] (d-major), Ps[128][AP]. AP=68
// gives conflict-free (4g+t) fragment addressing.
// ---------------------------------------------------------------------------
#define ATTN_SMEM_BYTES ((128 + 64 + 64 + 128) * AP * 4)

__global__ __launch_bounds__(256) void attn_tc_kernel(
    const int* __restrict__ mask, float* __restrict__ AO)
{
    extern __shared__ float sm[];
    float* Qs = sm;                   // [128][AP]
    float* Ks = Qs + 128 * AP;        // [64][AP]
    float* Vt = Ks + 64 * AP;         // [64][AP], Vt[d][j]
    float* Ps = Vt + 64 * AP;         // [128][AP]

    int tid  = threadIdx.x;
    int lane = tid & 31, warp = tid >> 5;
    int g = lane >> 2, t = lane & 3;
    int q0 = blockIdx.x * 128;
    int h  = blockIdx.y;
    int b  = blockIdx.z;

    const float* Qb = g_Qh + (size_t)((b * PH + h) * PS) * PHD;
    const float* Kb = g_Kh + (size_t)((b * PH + h) * PS) * PHD;
    const float* Vb = g_Vh + (size_t)((b * PH + h) * PS) * PHD;

    // stage Q (tf32-rounded): thread row = tid/2, half-row = 32 floats
    {
        int row = tid >> 1, c0 = (tid & 1) * 32;
        const float* src = Qb + (q0 + row) * 64 + c0;
        float* dst = Qs + row * AP + c0;
#pragma unroll
        for (int i = 0; i < 8; i++) {
            float4 v = *(const float4*)(src + i * 4);
            v.x = f2tf32f(v.x); v.y = f2tf32f(v.y);
            v.z = f2tf32f(v.z); v.w = f2tf32f(v.w);
            *(float4*)(dst + i * 4) = v;
        }
    }

    int qrow = warp * 16 + g;   // low fragment row within CTA tile
    bool v0 = mask[b * PS + q0 + qrow] != 0;
    bool v1 = mask[b * PS + q0 + qrow + 8] != 0;

    float m0 = -INFINITY, m1 = -INFINITY, l0 = 0.f, l1 = 0.f;
    float o[8][4];
#pragma unroll
    for (int nt = 0; nt < 8; nt++)
#pragma unroll
        for (int i = 0; i < 4; i++) o[nt][i] = 0.f;

    int krow  = tid >> 2;          // 0..63 (K/V staging row = key index)
    int kcol  = (tid & 3) * 16;    // K staging col base
    int dbase = (tid & 3) * 4;     // V transpose d base (interleaved)

    for (int j0 = 0; j0 < PS; j0 += 64) {
        __syncthreads();   // prior tile's Ks/Vt reads complete
        {
            const float* ks = Kb + (j0 + krow) * 64 + kcol;
            float* kd = Ks + krow * AP + kcol;
#pragma unroll
            for (int i = 0; i < 4; i++) {
                float4 v = *(const float4*)(ks + i * 4);
                v.x = f2tf32f(v.x); v.y = f2tf32f(v.y);
                v.z = f2tf32f(v.z); v.w = f2tf32f(v.w);
                *(float4*)(kd + i * 4) = v;
            }
            const float* vs = Vb + (j0 + krow) * 64;
#pragma unroll
            for (int kk = 0; kk < 4; kk++) {
                float4 v = *(const float4*)(vs + dbase + kk * 16);
                int d = dbase + kk * 16;
                Vt[(d + 0) * AP + krow] = f2tf32f(v.x);
                Vt[(d + 1) * AP + krow] = f2tf32f(v.y);
                Vt[(d + 2) * AP + krow] = f2tf32f(v.z);
                Vt[(d + 3) * AP + krow] = f2tf32f(v.w);
            }
        }
        __syncthreads();

        // S = Q K^T  (s[nt]: rows qrow/qrow+8, cols nt*8+2t, +1)
        float s[8][4];
#pragma unroll
        for (int nt = 0; nt < 8; nt++)
#pragma unroll
            for (int i = 0; i < 4; i++) s[nt][i] = 0.f;

#pragma unroll
        for (int kc = 0; kc < 8; kc++) {
            int qb_ = qrow * AP + kc * 8 + t;
            uint32_t a0 = __float_as_uint(Qs[qb_]);
            uint32_t a1 = __float_as_uint(Qs[qb_ + 8 * AP]);
            uint32_t a2 = __float_as_uint(Qs[qb_ + 4]);
            uint32_t a3 = __float_as_uint(Qs[qb_ + 8 * AP + 4]);
#pragma unroll
            for (int nt = 0; nt < 8; nt++) {
                int bb_ = (nt * 8 + g) * AP + kc * 8 + t;
                uint32_t b0 = __float_as_uint(Ks[bb_]);
                uint32_t b1 = __float_as_uint(Ks[bb_ + 4]);
                mma_tf32(s[nt], a0, a1, a2, a3, b0, b1);
            }
        }

        // scale + query-row mask
#pragma unroll
        for (int nt = 0; nt < 8; nt++) {
            s[nt][0] = v0 ? s[nt][0] * 0.125f : -1e9f;
            s[nt][1] = v0 ? s[nt][1] * 0.125f : -1e9f;
            s[nt][2] = v1 ? s[nt][2] * 0.125f : -1e9f;
            s[nt][3] = v1 ? s[nt][3] * 0.125f : -1e9f;
        }

        // tile row maxes (reduce across the 4 t-lanes of each row)
        float tm0 = -INFINITY, tm1 = -INFINITY;
#pragma unroll
        for (int nt = 0; nt < 8; nt++) {
            tm0 = fmaxf(tm0, fmaxf(s[nt][0], s[nt][1]));
            tm1 = fmaxf(tm1, fmaxf(s[nt][2], s[nt][3]));
        }
        tm0 = fmaxf(tm0, __shfl_xor_sync(0xffffffffu, tm0, 1));
        tm0 = fmaxf(tm0, __shfl_xor_sync(0xffffffffu, tm0, 2));
        tm1 = fmaxf(tm1, __shfl_xor_sync(0xffffffffu, tm1, 1));
        tm1 = fmaxf(tm1, __shfl_xor_sync(0xffffffffu, tm1, 2));

        // online update
        float mn0 = fmaxf(m0, tm0), mn1 = fmaxf(m1, tm1);
        float cr0 = __expf(m0 - mn0), cr1 = __expf(m1 - mn1);
        m0 = mn0; m1 = mn1;
        l0 *= cr0; l1 *= cr1;
#pragma unroll
        for (int nt = 0; nt < 8; nt++) {
            o[nt][0] *= cr0; o[nt][1] *= cr0;
            o[nt][2] *= cr1; o[nt][3] *= cr1;
        }

        // probabilities (tf32-rounded; same values feed l and PV)
#pragma unroll
        for (int nt = 0; nt < 8; nt++) {
            float p0 = f2tf32f(__expf(s[nt][0] - m0));
            float p1 = f2tf32f(__expf(s[nt][1] - m0));
            float p2 = f2tf32f(__expf(s[nt][2] - m1));
            float p3 = f2tf32f(__expf(s[nt][3] - m1));
            l0 += p0 + p1;
            l1 += p2 + p3;
            int col = nt * 8 + 2 * t;
            Ps[qrow * AP + col]           = p0;
            Ps[qrow * AP + col + 1]       = p1;
            Ps[(qrow + 8) * AP + col]     = p2;
            Ps[(qrow + 8) * AP + col + 1] = p3;
        }
        __syncwarp();   // P rows are warp-private; order STS -> LDS in-warp

        // O += P V   (A = Ps rows, B = Vt[d][j])
#pragma unroll
        for (int kc = 0; kc < 8; kc++) {
            int pb_ = qrow * AP + kc * 8 + t;
            uint32_t a0 = __float_as_uint(Ps[pb_]);
            uint32_t a1 = __float_as_uint(Ps[pb_ + 8 * AP]);
            uint32_t a2 = __float_as_uint(Ps[pb_ + 4]);
            uint32_t a3 = __float_as_uint(Ps[pb_ + 8 * AP + 4]);
#pragma unroll
            for (int nt = 0; nt < 8; nt++) {
                int bb_ = (nt * 8 + g) * AP + kc * 8 + t;
                uint32_t b0 = __float_as_uint(Vt[bb_]);
                uint32_t b1 = __float_as_uint(Vt[bb_ + 4]);
                mma_tf32(o[nt], a0, a1, a2, a3, b0, b1);
            }
        }
        __syncwarp();   // PV reads done before next tile's P stores
    }

    // final row sums (across the 4 t-lanes) and output
    l0 += __shfl_xor_sync(0xffffffffu, l0, 1);
    l0 += __shfl_xor_sync(0xffffffffu, l0, 2);
    l1 += __shfl_xor_sync(0xffffffffu, l1, 1);
    l1 += __shfl_xor_sync(0xffffffffu, l1, 2);
    float inv0 = 1.f / l0, inv1 = 1.f / l1;

    float* out0 = AO + (size_t)(b * PS + q0 + qrow) * PD + h * 64;
    float* out1 = out0 + (size_t)8 * PD;
#pragma unroll
    for (int nt = 0; nt < 8; nt++) {
        int d = nt * 8 + 2 * t;
        *(float2*)(out0 + d) = make_float2(o[nt][0] * inv0, o[nt][1] * inv0);
        *(float2*)(out1 + d) = make_float2(o[nt][2] * inv1, o[nt][3] * inv1);
    }
}

// ---------------------------------------------------------------------------
extern "C" void kernel_launch(void* const* d_in, const int* in_sizes, int n_in,
                              void* d_out, int out_size)
{
    const float* q   = (const float*)d_in[0];
    const float* k   = (const float*)d_in[1];
    const float* v   = (const float*)d_in[2];
    const float* Wq  = (const float*)d_in[3];
    const float* bq  = (const float*)d_in[4];
    const float* Wk  = (const float*)d_in[5];
    const float* bk  = (const float*)d_in[6];
    const float* Wv  = (const float*)d_in[7];
    const float* bv  = (const float*)d_in[8];
    const float* Wo  = (const float*)d_in[9];
    const float* bo  = (const float*)d_in[10];
    const int*   msk = (const int*)d_in[11];
    float* out = (float*)d_out;

    float *qh, *kh, *vh, *ao;
    cudaGetSymbolAddress((void**)&qh, g_Qh);
    cudaGetSymbolAddress((void**)&kh, g_Kh);
    cudaGetSymbolAddress((void**)&vh, g_Vh);
    cudaGetSymbolAddress((void**)&ao, g_AO);

    dim3 pgrid(PD / 128, PM / 128);   // (8, 64)
    dim3 pblk(256);

    proj_tc_kernel<<<pgrid, pblk>>>(q, Wq, bq, qh, 1);
    proj_tc_kernel<<<pgrid, pblk>>>(k, Wk, bk, kh, 1);
    proj_tc_kernel<<<pgrid, pblk>>>(v, Wv, bv, vh, 1);

    cudaFuncSetAttribute(attn_tc_kernel,
                         cudaFuncAttributeMaxDynamicSharedMemorySize,
                         ATTN_SMEM_BYTES);
    attn_tc_kernel<<<dim3(PS / 128, PH, PB), 256, ATTN_SMEM_BYTES>>>(msk, ao);

    proj_tc_kernel<<<pgrid, pblk>>>(ao, Wo, bo, out, 0);
}

// round 9
// speedup vs baseline: 2.7220x; 1.2136x over previous
#include <cuda_runtime.h>
#include <cuda_bf16.h>
#include <math.h>
#include <stdint.h>

// Problem constants
#define PB 4
#define PS 2048
#define PD 1024
#define PH 16
#define PHD 64
#define PM (PB*PS)        // 8192 tokens
#define AP 68             // attention smem pitch (floats)

// Scratch (allocation-free rule: __device__ globals)
__device__ float g_Qh[PB*PH*PS*PHD];   // [B,H,S,HD]
__device__ float g_Kh[PB*PH*PS*PHD];
__device__ float g_Vh[PB*PH*PS*PHD];
__device__ float g_AO[PB*PS*PD];       // [B,S,D]

// Packed bf16 hi/lo planes (2 bf16 per uint32, k-pairs)
__device__ uint32_t g_qhS[PM*PD/2], g_qlS[PM*PD/2];
__device__ uint32_t g_khS[PM*PD/2], g_klS[PM*PD/2];
__device__ uint32_t g_vhS[PM*PD/2], g_vlS[PM*PD/2];
__device__ uint32_t g_aohS[PM*PD/2], g_aolS[PM*PD/2];
__device__ uint32_t g_WqhS[PD*PD/2], g_WqlS[PD*PD/2];
__device__ uint32_t g_WkhS[PD*PD/2], g_WklS[PD*PD/2];
__device__ uint32_t g_WvhS[PD*PD/2], g_WvlS[PD*PD/2];
__device__ uint32_t g_WohS[PD*PD/2], g_WolS[PD*PD/2];

// ---------------------------------------------------------------------------
// Helpers
// ---------------------------------------------------------------------------
__device__ __forceinline__ float f2tf32f(float x) {
    uint32_t r;
    asm("cvt.rna.tf32.f32 %0, %1;" : "=r"(r) : "f"(x));
    return __uint_as_float(r);
}

__device__ __forceinline__ void mma_tf32(float c[4],
    uint32_t a0, uint32_t a1, uint32_t a2, uint32_t a3,
    uint32_t b0, uint32_t b1)
{
    asm volatile(
        "mma.sync.aligned.m16n8k8.row.col.f32.tf32.tf32.f32 "
        "{%0,%1,%2,%3}, {%4,%5,%6,%7}, {%8,%9}, {%0,%1,%2,%3};"
        : "+f"(c[0]), "+f"(c[1]), "+f"(c[2]), "+f"(c[3])
        : "r"(a0), "r"(a1), "r"(a2), "r"(a3), "r"(b0), "r"(b1));
}

__device__ __forceinline__ void mma_bf16(float c[4],
    uint32_t a0, uint32_t a1, uint32_t a2, uint32_t a3,
    uint32_t b0, uint32_t b1)
{
    asm volatile(
        "mma.sync.aligned.m16n8k16.row.col.f32.bf16.bf16.f32 "
        "{%0,%1,%2,%3}, {%4,%5,%6,%7}, {%8,%9}, {%0,%1,%2,%3};"
        : "+f"(c[0]), "+f"(c[1]), "+f"(c[2]), "+f"(c[3])
        : "r"(a0), "r"(a1), "r"(a2), "r"(a3), "r"(b0), "r"(b1));
}

// split two floats into packed bf16x2 hi and lo words
__device__ __forceinline__ void split2(float x, float y,
                                       uint32_t& hi, uint32_t& lo)
{
    __nv_bfloat16 xh = __float2bfloat16_rn(x);
    __nv_bfloat16 yh = __float2bfloat16_rn(y);
    float xr = x - __bfloat162float(xh);
    float yr = y - __bfloat162float(yh);
    __nv_bfloat162 h = __halves2bfloat162(xh, yh);
    __nv_bfloat162 l = __floats2bfloat162_rn(xr, yr);
    hi = *reinterpret_cast<uint32_t*>(&h);
    lo = *reinterpret_cast<uint32_t*>(&l);
}

#define CP_ASYNC16(saddr, gptr) \
    asm volatile("cp.async.cg.shared.global [%0], [%1], 16;" \
                 :: "r"(saddr), "l"(gptr))
#define CP_COMMIT() asm volatile("cp.async.commit_group;")
#define CP_WAIT1()  asm volatile("cp.async.wait_group 1;")
#define CP_WAIT0()  asm volatile("cp.async.wait_group 0;")

// ---------------------------------------------------------------------------
// Elementwise bf16 hi/lo split: src fp32 -> packed hi/lo planes.
// Each thread handles 8 floats (one uint4 of hi words + one of lo).
// ---------------------------------------------------------------------------
__global__ __launch_bounds__(256) void split_kernel(
    const float* __restrict__ src, uint32_t* __restrict__ hi,
    uint32_t* __restrict__ lo)
{
    int idx = blockIdx.x * blockDim.x + threadIdx.x;
    const float4* s = (const float4*)src + (size_t)idx * 2;
    float4 a = s[0], b = s[1];
    uint32_t h[4], l[4];
    split2(a.x, a.y, h[0], l[0]);
    split2(a.z, a.w, h[1], l[1]);
    split2(b.x, b.y, h[2], l[2]);
    split2(b.z, b.w, h[3], l[3]);
    ((uint4*)hi)[idx] = make_uint4(h[0], h[1], h[2], h[3]);
    ((uint4*)lo)[idx] = make_uint4(l[0], l[1], l[2], l[3]);
}

// ---------------------------------------------------------------------------
// Projection GEMM v2: pre-split bf16 planes, cp.async double buffering.
//   out[M,N] ~= Xh*Wh + Xh*Wl + Xl*Wh + bias     (3-term bf16, m16n8k16)
// BM=128, BN=128, BK=32 (16 words). 256 threads = 8 warps, warp tile 64x32.
// smem: 2 stages x 4 planes x [128][20] uint32 (pitch 20 -> conflict-free).
// ---------------------------------------------------------------------------
#define PSTG (4*2560)               // words per stage
#define PROJ_SMEM_BYTES (2*PSTG*4)  // 81920

__global__ __launch_bounds__(256) void proj2_kernel(
    const uint32_t* __restrict__ Xhg, const uint32_t* __restrict__ Xlg,
    const uint32_t* __restrict__ Whg, const uint32_t* __restrict__ Wlg,
    const float* __restrict__ bias, float* __restrict__ outp, int head_split)
{
    extern __shared__ uint32_t dsm[];

    int tid  = threadIdx.x;
    int lane = tid & 31, warp = tid >> 5;
    int g = lane >> 2, t = lane & 3;
    int m0 = blockIdx.y * 128, n0 = blockIdx.x * 128;
    int wm0 = (warp >> 2) * 64;     // 0 or 64
    int wn0 = (warp & 3) * 32;      // 0,32,64,96

    // cp.async chunk plan: 2048 16B-chunks/stage, 8 per thread.
    // cid = ch*256 + tid; plane = cid>>9; row = (cid>>2)&127; cgroup = cid&3.
    const uint32_t* gsrc[4] = {Xhg, Xlg, Whg, Wlg};
    uint32_t sdst[8];
    const uint32_t* gptr[8];
    uint32_t sbase = (uint32_t)__cvta_generic_to_shared(dsm);
#pragma unroll
    for (int ch = 0; ch < 8; ch++) {
        int cid = ch * 256 + tid;
        int p   = cid >> 9;
        int r   = (cid >> 2) & 127;
        int cg  = cid & 3;
        sdst[ch] = sbase + (uint32_t)(p * 2560 + r * 20 + cg * 4) * 4u;
        int row_g = (p < 2 ? m0 : n0) + r;
        gptr[ch] = gsrc[p] + (size_t)row_g * 512 + cg * 4;
    }

    float c[4][4][4];
#pragma unroll
    for (int mt = 0; mt < 4; mt++)
#pragma unroll
        for (int nt = 0; nt < 4; nt++)
#pragma unroll
            for (int i = 0; i < 4; i++) c[mt][nt][i] = 0.f;

    // prologue: stage 0 <- k-words [0,16)
#pragma unroll
    for (int ch = 0; ch < 8; ch++)
        CP_ASYNC16(sdst[ch], gptr[ch]);
    CP_COMMIT();

    for (int it = 0; it < 32; it++) {
        int cur = it & 1;
        if (it + 1 < 32) {
            uint32_t soff = (uint32_t)(cur ^ 1) * (PSTG * 4u);
            int koff = (it + 1) * 16;   // words
#pragma unroll
            for (int ch = 0; ch < 8; ch++)
                CP_ASYNC16(sdst[ch] + soff, gptr[ch] + koff);
            CP_COMMIT();
            CP_WAIT1();
        } else {
            CP_WAIT0();
        }
        __syncthreads();

        const uint32_t* Xh = dsm + cur * PSTG;
        const uint32_t* Xl = Xh + 2560;
        const uint32_t* Wh = Xh + 5120;
        const uint32_t* Wl = Xh + 7680;

#pragma unroll
        for (int kc2 = 0; kc2 < 16; kc2 += 8) {   // two k16 chunks
            uint32_t ah[4][4], al[4][4];
#pragma unroll
            for (int mt = 0; mt < 4; mt++) {
                int base = (wm0 + g + mt * 16) * 20 + kc2 + t;
                ah[mt][0] = Xh[base];
                ah[mt][1] = Xh[base + 160];      // row + 8
                ah[mt][2] = Xh[base + 4];
                ah[mt][3] = Xh[base + 164];
                al[mt][0] = Xl[base];
                al[mt][1] = Xl[base + 160];
                al[mt][2] = Xl[base + 4];
                al[mt][3] = Xl[base + 164];
            }
            uint32_t bh[4][2], bl[4][2];
#pragma unroll
            for (int nt = 0; nt < 4; nt++) {
                int base = (wn0 + nt * 8 + g) * 20 + kc2 + t;
                bh[nt][0] = Wh[base];
                bh[nt][1] = Wh[base + 4];
                bl[nt][0] = Wl[base];
                bl[nt][1] = Wl[base + 4];
            }
#pragma unroll
            for (int mt = 0; mt < 4; mt++)
#pragma unroll
                for (int nt = 0; nt < 4; nt++) {
                    mma_bf16(c[mt][nt], ah[mt][0], ah[mt][1], ah[mt][2], ah[mt][3],
                             bh[nt][0], bh[nt][1]);
                    mma_bf16(c[mt][nt], ah[mt][0], ah[mt][1], ah[mt][2], ah[mt][3],
                             bl[nt][0], bl[nt][1]);
                    mma_bf16(c[mt][nt], al[mt][0], al[mt][1], al[mt][2], al[mt][3],
                             bh[nt][0], bh[nt][1]);
                }
        }
        __syncthreads();   // all warps done with 'cur' before it is refilled
    }

    // epilogue: bias + store (float2 per row-half)
#pragma unroll
    for (int nt = 0; nt < 4; nt++) {
        int n = n0 + wn0 + nt * 8 + 2 * t;
        float b0v = bias[n], b1v = bias[n + 1];
#pragma unroll
        for (int mt = 0; mt < 4; mt++) {
            int r0 = m0 + wm0 + mt * 16 + g;
            int r1 = r0 + 8;
            float2 v0 = make_float2(c[mt][nt][0] + b0v, c[mt][nt][1] + b1v);
            float2 v1 = make_float2(c[mt][nt][2] + b0v, c[mt][nt][3] + b1v);
            if (head_split) {
                int hh = n >> 6, hd = n & 63;
                int bb0 = r0 >> 11, s0 = r0 & 2047;
                int bb1 = r1 >> 11, s1 = r1 & 2047;
                *(float2*)&outp[(((bb0 * PH + hh) * PS + s0) << 6) + hd] = v0;
                *(float2*)&outp[(((bb1 * PH + hh) * PS + s1) << 6) + hd] = v1;
            } else {
                *(float2*)&outp[r0 * PD + n] = v0;
                *(float2*)&outp[r1 * PD + n] = v1;
            }
        }
    }
}

// ---------------------------------------------------------------------------
// Tensor-core flash attention (tf32 single-pass MMAs, fp32 softmax).
// grid = (S/128, H, B), 256 threads = 8 warps. CTA tile: 128 q x 64 keys.
// (unchanged from R6 — validated at 735us, rel_err-dominant tf32 path)
// ---------------------------------------------------------------------------
#define ATTN_SMEM_BYTES ((128 + 64 + 64 + 128) * AP * 4)

__global__ __launch_bounds__(256) void attn_tc_kernel(
    const int* __restrict__ mask, float* __restrict__ AO)
{
    extern __shared__ float sm[];
    float* Qs = sm;                   // [128][AP]
    float* Ks = Qs + 128 * AP;        // [64][AP]
    float* Vt = Ks + 64 * AP;         // [64][AP], Vt[d][j]
    float* Ps = Vt + 64 * AP;         // [128][AP]

    int tid  = threadIdx.x;
    int lane = tid & 31, warp = tid >> 5;
    int g = lane >> 2, t = lane & 3;
    int q0 = blockIdx.x * 128;
    int h  = blockIdx.y;
    int b  = blockIdx.z;

    const float* Qb = g_Qh + (size_t)((b * PH + h) * PS) * PHD;
    const float* Kb = g_Kh + (size_t)((b * PH + h) * PS) * PHD;
    const float* Vb = g_Vh + (size_t)((b * PH + h) * PS) * PHD;

    // stage Q (tf32-rounded): thread row = tid/2, half-row = 32 floats
    {
        int row = tid >> 1, c0 = (tid & 1) * 32;
        const float* src = Qb + (q0 + row) * 64 + c0;
        float* dst = Qs + row * AP + c0;
#pragma unroll
        for (int i = 0; i < 8; i++) {
            float4 v = *(const float4*)(src + i * 4);
            v.x = f2tf32f(v.x); v.y = f2tf32f(v.y);
            v.z = f2tf32f(v.z); v.w = f2tf32f(v.w);
            *(float4*)(dst + i * 4) = v;
        }
    }

    int qrow = warp * 16 + g;   // low fragment row within CTA tile
    bool v0 = mask[b * PS + q0 + qrow] != 0;
    bool v1 = mask[b * PS + q0 + qrow + 8] != 0;

    float m0 = -INFINITY, m1 = -INFINITY, l0 = 0.f, l1 = 0.f;
    float o[8][4];
#pragma unroll
    for (int nt = 0; nt < 8; nt++)
#pragma unroll
        for (int i = 0; i < 4; i++) o[nt][i] = 0.f;

    int krow  = tid >> 2;          // 0..63 (K/V staging row = key index)
    int kcol  = (tid & 3) * 16;    // K staging col base
    int dbase = (tid & 3) * 4;     // V transpose d base (interleaved)

    for (int j0 = 0; j0 < PS; j0 += 64) {
        __syncthreads();   // prior tile's Ks/Vt reads complete
        {
            const float* ks = Kb + (j0 + krow) * 64 + kcol;
            float* kd = Ks + krow * AP + kcol;
#pragma unroll
            for (int i = 0; i < 4; i++) {
                float4 v = *(const float4*)(ks + i * 4);
                v.x = f2tf32f(v.x); v.y = f2tf32f(v.y);
                v.z = f2tf32f(v.z); v.w = f2tf32f(v.w);
                *(float4*)(kd + i * 4) = v;
            }
            const float* vs = Vb + (j0 + krow) * 64;
#pragma unroll
            for (int kk = 0; kk < 4; kk++) {
                float4 v = *(const float4*)(vs + dbase + kk * 16);
                int d = dbase + kk * 16;
                Vt[(d + 0) * AP + krow] = f2tf32f(v.x);
                Vt[(d + 1) * AP + krow] = f2tf32f(v.y);
                Vt[(d + 2) * AP + krow] = f2tf32f(v.z);
                Vt[(d + 3) * AP + krow] = f2tf32f(v.w);
            }
        }
        __syncthreads();

        // S = Q K^T  (s[nt]: rows qrow/qrow+8, cols nt*8+2t, +1)
        float s[8][4];
#pragma unroll
        for (int nt = 0; nt < 8; nt++)
#pragma unroll
            for (int i = 0; i < 4; i++) s[nt][i] = 0.f;

#pragma unroll
        for (int kc = 0; kc < 8; kc++) {
            int qb_ = qrow * AP + kc * 8 + t;
            uint32_t a0 = __float_as_uint(Qs[qb_]);
            uint32_t a1 = __float_as_uint(Qs[qb_ + 8 * AP]);
            uint32_t a2 = __float_as_uint(Qs[qb_ + 4]);
            uint32_t a3 = __float_as_uint(Qs[qb_ + 8 * AP + 4]);
#pragma unroll
            for (int nt = 0; nt < 8; nt++) {
                int bb_ = (nt * 8 + g) * AP + kc * 8 + t;
                uint32_t b0 = __float_as_uint(Ks[bb_]);
                uint32_t b1 = __float_as_uint(Ks[bb_ + 4]);
                mma_tf32(s[nt], a0, a1, a2, a3, b0, b1);
            }
        }

        // scale + query-row mask
#pragma unroll
        for (int nt = 0; nt < 8; nt++) {
            s[nt][0] = v0 ? s[nt][0] * 0.125f : -1e9f;
            s[nt][1] = v0 ? s[nt][1] * 0.125f : -1e9f;
            s[nt][2] = v1 ? s[nt][2] * 0.125f : -1e9f;
            s[nt][3] = v1 ? s[nt][3] * 0.125f : -1e9f;
        }

        // tile row maxes (reduce across the 4 t-lanes of each row)
        float tm0 = -INFINITY, tm1 = -INFINITY;
#pragma unroll
        for (int nt = 0; nt < 8; nt++) {
            tm0 = fmaxf(tm0, fmaxf(s[nt][0], s[nt][1]));
            tm1 = fmaxf(tm1, fmaxf(s[nt][2], s[nt][3]));
        }
        tm0 = fmaxf(tm0, __shfl_xor_sync(0xffffffffu, tm0, 1));
        tm0 = fmaxf(tm0, __shfl_xor_sync(0xffffffffu, tm0, 2));
        tm1 = fmaxf(tm1, __shfl_xor_sync(0xffffffffu, tm1, 1));
        tm1 = fmaxf(tm1, __shfl_xor_sync(0xffffffffu, tm1, 2));

        // online update
        float mn0 = fmaxf(m0, tm0), mn1 = fmaxf(m1, tm1);
        float cr0 = __expf(m0 - mn0), cr1 = __expf(m1 - mn1);
        m0 = mn0; m1 = mn1;
        l0 *= cr0; l1 *= cr1;
#pragma unroll
        for (int nt = 0; nt < 8; nt++) {
            o[nt][0] *= cr0; o[nt][1] *= cr0;
            o[nt][2] *= cr1; o[nt][3] *= cr1;
        }

        // probabilities (tf32-rounded; same values feed l and PV)
#pragma unroll
        for (int nt = 0; nt < 8; nt++) {
            float p0 = f2tf32f(__expf(s[nt][0] - m0));
            float p1 = f2tf32f(__expf(s[nt][1] - m0));
            float p2 = f2tf32f(__expf(s[nt][2] - m1));
            float p3 = f2tf32f(__expf(s[nt][3] - m1));
            l0 += p0 + p1;
            l1 += p2 + p3;
            int col = nt * 8 + 2 * t;
            Ps[qrow * AP + col]           = p0;
            Ps[qrow * AP + col + 1]       = p1;
            Ps[(qrow + 8) * AP + col]     = p2;
            Ps[(qrow + 8) * AP + col + 1] = p3;
        }
        __syncwarp();   // P rows are warp-private; order STS -> LDS in-warp

        // O += P V   (A = Ps rows, B = Vt[d][j])
#pragma unroll
        for (int kc = 0; kc < 8; kc++) {
            int pb_ = qrow * AP + kc * 8 + t;
            uint32_t a0 = __float_as_uint(Ps[pb_]);
            uint32_t a1 = __float_as_uint(Ps[pb_ + 8 * AP]);
            uint32_t a2 = __float_as_uint(Ps[pb_ + 4]);
            uint32_t a3 = __float_as_uint(Ps[pb_ + 8 * AP + 4]);
#pragma unroll
            for (int nt = 0; nt < 8; nt++) {
                int bb_ = (nt * 8 + g) * AP + kc * 8 + t;
                uint32_t b0 = __float_as_uint(Vt[bb_]);
                uint32_t b1 = __float_as_uint(Vt[bb_ + 4]);
                mma_tf32(o[nt], a0, a1, a2, a3, b0, b1);
            }
        }
        __syncwarp();   // PV reads done before next tile's P stores
    }

    // final row sums (across the 4 t-lanes) and output
    l0 += __shfl_xor_sync(0xffffffffu, l0, 1);
    l0 += __shfl_xor_sync(0xffffffffu, l0, 2);
    l1 += __shfl_xor_sync(0xffffffffu, l1, 1);
    l1 += __shfl_xor_sync(0xffffffffu, l1, 2);
    float inv0 = 1.f / l0, inv1 = 1.f / l1;

    float* out0 = AO + (size_t)(b * PS + q0 + qrow) * PD + h * 64;
    float* out1 = out0 + (size_t)8 * PD;
#pragma unroll
    for (int nt = 0; nt < 8; nt++) {
        int d = nt * 8 + 2 * t;
        *(float2*)(out0 + d) = make_float2(o[nt][0] * inv0, o[nt][1] * inv0);
        *(float2*)(out1 + d) = make_float2(o[nt][2] * inv1, o[nt][3] * inv1);
    }
}

// ---------------------------------------------------------------------------
extern "C" void kernel_launch(void* const* d_in, const int* in_sizes, int n_in,
                              void* d_out, int out_size)
{
    const float* q   = (const float*)d_in[0];
    const float* k   = (const float*)d_in[1];
    const float* v   = (const float*)d_in[2];
    const float* Wq  = (const float*)d_in[3];
    const float* bq  = (const float*)d_in[4];
    const float* Wk  = (const float*)d_in[5];
    const float* bk  = (const float*)d_in[6];
    const float* Wv  = (const float*)d_in[7];
    const float* bv  = (const float*)d_in[8];
    const float* Wo  = (const float*)d_in[9];
    const float* bo  = (const float*)d_in[10];
    const int*   msk = (const int*)d_in[11];
    float* out = (float*)d_out;

    float *qh, *kh, *vh, *ao;
    cudaGetSymbolAddress((void**)&qh, g_Qh);
    cudaGetSymbolAddress((void**)&kh, g_Kh);
    cudaGetSymbolAddress((void**)&vh, g_Vh);
    cudaGetSymbolAddress((void**)&ao, g_AO);

    uint32_t *qhS, *qlS, *khS, *klS, *vhS, *vlS, *aohS, *aolS;
    uint32_t *WqhS, *WqlS, *WkhS, *WklS, *WvhS, *WvlS, *WohS, *WolS;
    cudaGetSymbolAddress((void**)&qhS,  g_qhS);
    cudaGetSymbolAddress((void**)&qlS,  g_qlS);
    cudaGetSymbolAddress((void**)&khS,  g_khS);
    cudaGetSymbolAddress((void**)&klS,  g_klS);
    cudaGetSymbolAddress((void**)&vhS,  g_vhS);
    cudaGetSymbolAddress((void**)&vlS,  g_vlS);
    cudaGetSymbolAddress((void**)&aohS, g_aohS);
    cudaGetSymbolAddress((void**)&aolS, g_aolS);
    cudaGetSymbolAddress((void**)&WqhS, g_WqhS);
    cudaGetSymbolAddress((void**)&WqlS, g_WqlS);
    cudaGetSymbolAddress((void**)&WkhS, g_WkhS);
    cudaGetSymbolAddress((void**)&WklS, g_WklS);
    cudaGetSymbolAddress((void**)&WvhS, g_WvhS);
    cudaGetSymbolAddress((void**)&WvlS, g_WvlS);
    cudaGetSymbolAddress((void**)&WohS, g_WohS);
    cudaGetSymbolAddress((void**)&WolS, g_WolS);

    const int NX4 = PM * PD / 8;   // uint4 groups per activation tensor
    const int NW4 = PD * PD / 8;   // per weight tensor

    split_kernel<<<NX4 / 256, 256>>>(q,  qhS, qlS);
    split_kernel<<<NX4 / 256, 256>>>(k,  khS, klS);
    split_kernel<<<NX4 / 256, 256>>>(v,  vhS, vlS);
    split_kernel<<<NW4 / 256, 256>>>(Wq, WqhS, WqlS);
    split_kernel<<<NW4 / 256, 256>>>(Wk, WkhS, WklS);
    split_kernel<<<NW4 / 256, 256>>>(Wv, WvhS, WvlS);
    split_kernel<<<NW4 / 256, 256>>>(Wo, WohS, WolS);

    dim3 pgrid(PD / 128, PM / 128);   // (8, 64)
    dim3 pblk(256);
    cudaFuncSetAttribute(proj2_kernel,
                         cudaFuncAttributeMaxDynamicSharedMemorySize,
                         PROJ_SMEM_BYTES);

    proj2_kernel<<<pgrid, pblk, PROJ_SMEM_BYTES>>>(qhS, qlS, WqhS, WqlS, bq, qh, 1);
    proj2_kernel<<<pgrid, pblk, PROJ_SMEM_BYTES>>>(khS, klS, WkhS, WklS, bk, kh, 1);
    proj2_kernel<<<pgrid, pblk, PROJ_SMEM_BYTES>>>(vhS, vlS, WvhS, WvlS, bv, vh, 1);

    cudaFuncSetAttribute(attn_tc_kernel,
                         cudaFuncAttributeMaxDynamicSharedMemorySize,
                         ATTN_SMEM_BYTES);
    attn_tc_kernel<<<dim3(PS / 128, PH, PB), 256, ATTN_SMEM_BYTES>>>(msk, ao);

    split_kernel<<<NX4 / 256, 256>>>(ao, aohS, aolS);
    proj2_kernel<<<pgrid, pblk, PROJ_SMEM_BYTES>>>(aohS, aolS, WohS, WolS, bo, out, 0);
}

// round 10
// speedup vs baseline: 2.7244x; 1.0009x over previous
#include <cuda_runtime.h>
#include <cuda_bf16.h>
#include <math.h>
#include <stdint.h>

// Problem constants
#define PB 4
#define PS 2048
#define PD 1024
#define PH 16
#define PHD 64
#define PM (PB*PS)        // 8192 tokens
#define AP 68             // attention smem pitch (floats)

// Scratch (allocation-free rule: __device__ globals)
__device__ float g_Qh[PB*PH*PS*PHD];   // [B,H,S,HD]
__device__ float g_Kh[PB*PH*PS*PHD];
__device__ float g_Vh[PB*PH*PS*PHD];
__device__ float g_AO[PB*PS*PD];       // [B,S,D]

// Packed bf16 hi/lo planes (2 bf16 per uint32, k-pairs)
__device__ uint32_t g_qhS[PM*PD/2], g_qlS[PM*PD/2];
__device__ uint32_t g_khS[PM*PD/2], g_klS[PM*PD/2];
__device__ uint32_t g_vhS[PM*PD/2], g_vlS[PM*PD/2];
__device__ uint32_t g_aohS[PM*PD/2], g_aolS[PM*PD/2];
__device__ uint32_t g_WqhS[PD*PD/2], g_WqlS[PD*PD/2];
__device__ uint32_t g_WkhS[PD*PD/2], g_WklS[PD*PD/2];
__device__ uint32_t g_WvhS[PD*PD/2], g_WvlS[PD*PD/2];
__device__ uint32_t g_WohS[PD*PD/2], g_WolS[PD*PD/2];

// ---------------------------------------------------------------------------
// Helpers
// ---------------------------------------------------------------------------
__device__ __forceinline__ float f2tf32f(float x) {
    uint32_t r;
    asm("cvt.rna.tf32.f32 %0, %1;" : "=r"(r) : "f"(x));
    return __uint_as_float(r);
}

__device__ __forceinline__ void mma_tf32(float c[4],
    uint32_t a0, uint32_t a1, uint32_t a2, uint32_t a3,
    uint32_t b0, uint32_t b1)
{
    asm volatile(
        "mma.sync.aligned.m16n8k8.row.col.f32.tf32.tf32.f32 "
        "{%0,%1,%2,%3}, {%4,%5,%6,%7}, {%8,%9}, {%0,%1,%2,%3};"
        : "+f"(c[0]), "+f"(c[1]), "+f"(c[2]), "+f"(c[3])
        : "r"(a0), "r"(a1), "r"(a2), "r"(a3), "r"(b0), "r"(b1));
}

__device__ __forceinline__ void mma_bf16(float c[4],
    uint32_t a0, uint32_t a1, uint32_t a2, uint32_t a3,
    uint32_t b0, uint32_t b1)
{
    asm volatile(
        "mma.sync.aligned.m16n8k16.row.col.f32.bf16.bf16.f32 "
        "{%0,%1,%2,%3}, {%4,%5,%6,%7}, {%8,%9}, {%0,%1,%2,%3};"
        : "+f"(c[0]), "+f"(c[1]), "+f"(c[2]), "+f"(c[3])
        : "r"(a0), "r"(a1), "r"(a2), "r"(a3), "r"(b0), "r"(b1));
}

// split two floats into packed bf16x2 hi and lo words
__device__ __forceinline__ void split2(float x, float y,
                                       uint32_t& hi, uint32_t& lo)
{
    __nv_bfloat16 xh = __float2bfloat16_rn(x);
    __nv_bfloat16 yh = __float2bfloat16_rn(y);
    float xr = x - __bfloat162float(xh);
    float yr = y - __bfloat162float(yh);
    __nv_bfloat162 h = __halves2bfloat162(xh, yh);
    __nv_bfloat162 l = __floats2bfloat162_rn(xr, yr);
    hi = *reinterpret_cast<uint32_t*>(&h);
    lo = *reinterpret_cast<uint32_t*>(&l);
}

#define CP_ASYNC16(saddr, gptr) \
    asm volatile("cp.async.cg.shared.global [%0], [%1], 16;" \
                 :: "r"(saddr), "l"(gptr))
#define CP_COMMIT() asm volatile("cp.async.commit_group;")
#define CP_WAIT1()  asm volatile("cp.async.wait_group 1;")
#define CP_WAIT0()  asm volatile("cp.async.wait_group 0;")

// ---------------------------------------------------------------------------
// Elementwise bf16 hi/lo split: src fp32 -> packed hi/lo planes.
// ---------------------------------------------------------------------------
__global__ __launch_bounds__(256) void split_kernel(
    const float* __restrict__ src, uint32_t* __restrict__ hi,
    uint32_t* __restrict__ lo)
{
    int idx = blockIdx.x * blockDim.x + threadIdx.x;
    const float4* s = (const float4*)src + (size_t)idx * 2;
    float4 a = s[0], b = s[1];
    uint32_t h[4], l[4];
    split2(a.x, a.y, h[0], l[0]);
    split2(a.z, a.w, h[1], l[1]);
    split2(b.x, b.y, h[2], l[2]);
    split2(b.z, b.w, h[3], l[3]);
    ((uint4*)hi)[idx] = make_uint4(h[0], h[1], h[2], h[3]);
    ((uint4*)lo)[idx] = make_uint4(l[0], l[1], l[2], l[3]);
}

// ---------------------------------------------------------------------------
// Projection GEMM v2: pre-split bf16 planes, cp.async double buffering.
// (unchanged from R9 — measured at legacy-mma roofline, ~182us each)
// ---------------------------------------------------------------------------
#define PSTG (4*2560)               // words per stage
#define PROJ_SMEM_BYTES (2*PSTG*4)  // 81920

__global__ __launch_bounds__(256) void proj2_kernel(
    const uint32_t* __restrict__ Xhg, const uint32_t* __restrict__ Xlg,
    const uint32_t* __restrict__ Whg, const uint32_t* __restrict__ Wlg,
    const float* __restrict__ bias, float* __restrict__ outp, int head_split)
{
    extern __shared__ uint32_t dsm[];

    int tid  = threadIdx.x;
    int lane = tid & 31, warp = tid >> 5;
    int g = lane >> 2, t = lane & 3;
    int m0 = blockIdx.y * 128, n0 = blockIdx.x * 128;
    int wm0 = (warp >> 2) * 64;     // 0 or 64
    int wn0 = (warp & 3) * 32;      // 0,32,64,96

    const uint32_t* gsrc[4] = {Xhg, Xlg, Whg, Wlg};
    uint32_t sdst[8];
    const uint32_t* gptr[8];
    uint32_t sbase = (uint32_t)__cvta_generic_to_shared(dsm);
#pragma unroll
    for (int ch = 0; ch < 8; ch++) {
        int cid = ch * 256 + tid;
        int p   = cid >> 9;
        int r   = (cid >> 2) & 127;
        int cg  = cid & 3;
        sdst[ch] = sbase + (uint32_t)(p * 2560 + r * 20 + cg * 4) * 4u;
        int row_g = (p < 2 ? m0 : n0) + r;
        gptr[ch] = gsrc[p] + (size_t)row_g * 512 + cg * 4;
    }

    float c[4][4][4];
#pragma unroll
    for (int mt = 0; mt < 4; mt++)
#pragma unroll
        for (int nt = 0; nt < 4; nt++)
#pragma unroll
            for (int i = 0; i < 4; i++) c[mt][nt][i] = 0.f;

#pragma unroll
    for (int ch = 0; ch < 8; ch++)
        CP_ASYNC16(sdst[ch], gptr[ch]);
    CP_COMMIT();

    for (int it = 0; it < 32; it++) {
        int cur = it & 1;
        if (it + 1 < 32) {
            uint32_t soff = (uint32_t)(cur ^ 1) * (PSTG * 4u);
            int koff = (it + 1) * 16;
#pragma unroll
            for (int ch = 0; ch < 8; ch++)
                CP_ASYNC16(sdst[ch] + soff, gptr[ch] + koff);
            CP_COMMIT();
            CP_WAIT1();
        } else {
            CP_WAIT0();
        }
        __syncthreads();

        const uint32_t* Xh = dsm + cur * PSTG;
        const uint32_t* Xl = Xh + 2560;
        const uint32_t* Wh = Xh + 5120;
        const uint32_t* Wl = Xh + 7680;

#pragma unroll
        for (int kc2 = 0; kc2 < 16; kc2 += 8) {
            uint32_t ah[4][4], al[4][4];
#pragma unroll
            for (int mt = 0; mt < 4; mt++) {
                int base = (wm0 + g + mt * 16) * 20 + kc2 + t;
                ah[mt][0] = Xh[base];
                ah[mt][1] = Xh[base + 160];
                ah[mt][2] = Xh[base + 4];
                ah[mt][3] = Xh[base + 164];
                al[mt][0] = Xl[base];
                al[mt][1] = Xl[base + 160];
                al[mt][2] = Xl[base + 4];
                al[mt][3] = Xl[base + 164];
            }
            uint32_t bh[4][2], bl[4][2];
#pragma unroll
            for (int nt = 0; nt < 4; nt++) {
                int base = (wn0 + nt * 8 + g) * 20 + kc2 + t;
                bh[nt][0] = Wh[base];
                bh[nt][1] = Wh[base + 4];
                bl[nt][0] = Wl[base];
                bl[nt][1] = Wl[base + 4];
            }
#pragma unroll
            for (int mt = 0; mt < 4; mt++)
#pragma unroll
                for (int nt = 0; nt < 4; nt++) {
                    mma_bf16(c[mt][nt], ah[mt][0], ah[mt][1], ah[mt][2], ah[mt][3],
                             bh[nt][0], bh[nt][1]);
                    mma_bf16(c[mt][nt], ah[mt][0], ah[mt][1], ah[mt][2], ah[mt][3],
                             bl[nt][0], bl[nt][1]);
                    mma_bf16(c[mt][nt], al[mt][0], al[mt][1], al[mt][2], al[mt][3],
                             bh[nt][0], bh[nt][1]);
                }
        }
        __syncthreads();
    }

#pragma unroll
    for (int nt = 0; nt < 4; nt++) {
        int n = n0 + wn0 + nt * 8 + 2 * t;
        float b0v = bias[n], b1v = bias[n + 1];
#pragma unroll
        for (int mt = 0; mt < 4; mt++) {
            int r0 = m0 + wm0 + mt * 16 + g;
            int r1 = r0 + 8;
            float2 v0 = make_float2(c[mt][nt][0] + b0v, c[mt][nt][1] + b1v);
            float2 v1 = make_float2(c[mt][nt][2] + b0v, c[mt][nt][3] + b1v);
            if (head_split) {
                int hh = n >> 6, hd = n & 63;
                int bb0 = r0 >> 11, s0 = r0 & 2047;
                int bb1 = r1 >> 11, s1 = r1 & 2047;
                *(float2*)&outp[(((bb0 * PH + hh) * PS + s0) << 6) + hd] = v0;
                *(float2*)&outp[(((bb1 * PH + hh) * PS + s1) << 6) + hd] = v1;
            } else {
                *(float2*)&outp[r0 * PD + n] = v0;
                *(float2*)&outp[r1 * PD + n] = v1;
            }
        }
    }
}

// ---------------------------------------------------------------------------
// Tensor-core flash attention v2 (tf32 MMAs, fp32 softmax).
// grid = (S/128, H, B), 128 threads = 4 warps. CTA tile: 128 q x 64 keys.
// Warp w owns 32 q rows (two m16 tiles) -> K/V fragment loads amortized 2x.
// smem: Qs[128][AP], Ks[64][AP], Vt[64][AP] (d-major), Ps[128][AP].
// ---------------------------------------------------------------------------
#define ATTN_SMEM_BYTES ((128 + 64 + 64 + 128) * AP * 4)

__global__ __launch_bounds__(128) void attn_tc_kernel(
    const int* __restrict__ mask, float* __restrict__ AO)
{
    extern __shared__ float sm[];
    float* Qs = sm;                   // [128][AP]
    float* Ks = Qs + 128 * AP;        // [64][AP]
    float* Vt = Ks + 64 * AP;         // [64][AP], Vt[d][j]
    float* Ps = Vt + 64 * AP;         // [128][AP]

    int tid  = threadIdx.x;
    int lane = tid & 31, warp = tid >> 5;   // warp 0..3
    int g = lane >> 2, t = lane & 3;
    int q0 = blockIdx.x * 128;
    int h  = blockIdx.y;
    int b  = blockIdx.z;

    const float* Qb = g_Qh + (size_t)((b * PH + h) * PS) * PHD;
    const float* Kb = g_Kh + (size_t)((b * PH + h) * PS) * PHD;
    const float* Vb = g_Vh + (size_t)((b * PH + h) * PS) * PHD;

    // stage Q (tf32-rounded): 128 rows, 128 threads, 2 segments
#pragma unroll
    for (int seg = 0; seg < 2; seg++) {
        int row = (tid >> 1) + seg * 64;
        int c0  = (tid & 1) * 32;
        const float* src = Qb + (q0 + row) * 64 + c0;
        float* dst = Qs + row * AP + c0;
#pragma unroll
        for (int i = 0; i < 8; i++) {
            float4 v = *(const float4*)(src + i * 4);
            v.x = f2tf32f(v.x); v.y = f2tf32f(v.y);
            v.z = f2tf32f(v.z); v.w = f2tf32f(v.w);
            *(float4*)(dst + i * 4) = v;
        }
    }

    // warp q rows: m-tile 0 at qA, qA+8; m-tile 1 at qA+16, qA+24
    int qA = warp * 32 + g;
    bool valid[4];   // [mt*2 + half]
    valid[0] = mask[b * PS + q0 + qA]      != 0;
    valid[1] = mask[b * PS + q0 + qA + 8]  != 0;
    valid[2] = mask[b * PS + q0 + qA + 16] != 0;
    valid[3] = mask[b * PS + q0 + qA + 24] != 0;

    float mx[4], lsum[4];
#pragma unroll
    for (int i = 0; i < 4; i++) { mx[i] = -INFINITY; lsum[i] = 0.f; }

    float o[2][8][4];
#pragma unroll
    for (int mt = 0; mt < 2; mt++)
#pragma unroll
        for (int nt = 0; nt < 8; nt++)
#pragma unroll
            for (int i = 0; i < 4; i++) o[mt][nt][i] = 0.f;

    // staging indices (128 threads)
    int srow = tid >> 1;            // 0..63
    int shalf = tid & 1;
    int scol = shalf * 32;

    for (int j0 = 0; j0 < PS; j0 += 64) {
        __syncthreads();   // prior tile's Ks/Vt reads complete
        {
            // K: row srow, cols scol..scol+31
            const float* ks = Kb + (j0 + srow) * 64 + scol;
            float* kd = Ks + srow * AP + scol;
#pragma unroll
            for (int i = 0; i < 8; i++) {
                float4 v = *(const float4*)(ks + i * 4);
                v.x = f2tf32f(v.x); v.y = f2tf32f(v.y);
                v.z = f2tf32f(v.z); v.w = f2tf32f(v.w);
                *(float4*)(kd + i * 4) = v;
            }
            // V transpose: thread covers d in [scol, scol+32), k-rotated by half
            const float* vs = Vb + (j0 + srow) * 64;
#pragma unroll
            for (int k = 0; k < 8; k++) {
                int kk = (k + shalf) & 7;
                int d = scol + kk * 4;
                float4 v = *(const float4*)(vs + d);
                Vt[(d + 0) * AP + srow] = f2tf32f(v.x);
                Vt[(d + 1) * AP + srow] = f2tf32f(v.y);
                Vt[(d + 2) * AP + srow] = f2tf32f(v.z);
                Vt[(d + 3) * AP + srow] = f2tf32f(v.w);
            }
        }
        __syncthreads();

        // S = Q K^T for both m-tiles, sharing K fragment loads
        float s[2][8][4];
#pragma unroll
        for (int mt = 0; mt < 2; mt++)
#pragma unroll
            for (int nt = 0; nt < 8; nt++)
#pragma unroll
                for (int i = 0; i < 4; i++) s[mt][nt][i] = 0.f;

#pragma unroll
        for (int kc = 0; kc < 8; kc++) {
            uint32_t a[2][4];
#pragma unroll
            for (int mt = 0; mt < 2; mt++) {
                int qb_ = (qA + mt * 16) * AP + kc * 8 + t;
                a[mt][0] = __float_as_uint(Qs[qb_]);
                a[mt][1] = __float_as_uint(Qs[qb_ + 8 * AP]);
                a[mt][2] = __float_as_uint(Qs[qb_ + 4]);
                a[mt][3] = __float_as_uint(Qs[qb_ + 8 * AP + 4]);
            }
#pragma unroll
            for (int nt = 0; nt < 8; nt++) {
                int bb_ = (nt * 8 + g) * AP + kc * 8 + t;
                uint32_t b0 = __float_as_uint(Ks[bb_]);
                uint32_t b1 = __float_as_uint(Ks[bb_ + 4]);
                mma_tf32(s[0][nt], a[0][0], a[0][1], a[0][2], a[0][3], b0, b1);
                mma_tf32(s[1][nt], a[1][0], a[1][1], a[1][2], a[1][3], b0, b1);
            }
        }

        // per-m-tile: mask, scale, online softmax, P store
#pragma unroll
        for (int mt = 0; mt < 2; mt++) {
            bool v0 = valid[mt * 2], v1 = valid[mt * 2 + 1];
#pragma unroll
            for (int nt = 0; nt < 8; nt++) {
                s[mt][nt][0] = v0 ? s[mt][nt][0] * 0.125f : -1e9f;
                s[mt][nt][1] = v0 ? s[mt][nt][1] * 0.125f : -1e9f;
                s[mt][nt][2] = v1 ? s[mt][nt][2] * 0.125f : -1e9f;
                s[mt][nt][3] = v1 ? s[mt][nt][3] * 0.125f : -1e9f;
            }
            float tm0 = -INFINITY, tm1 = -INFINITY;
#pragma unroll
            for (int nt = 0; nt < 8; nt++) {
                tm0 = fmaxf(tm0, fmaxf(s[mt][nt][0], s[mt][nt][1]));
                tm1 = fmaxf(tm1, fmaxf(s[mt][nt][2], s[mt][nt][3]));
            }
            tm0 = fmaxf(tm0, __shfl_xor_sync(0xffffffffu, tm0, 1));
            tm0 = fmaxf(tm0, __shfl_xor_sync(0xffffffffu, tm0, 2));
            tm1 = fmaxf(tm1, __shfl_xor_sync(0xffffffffu, tm1, 1));
            tm1 = fmaxf(tm1, __shfl_xor_sync(0xffffffffu, tm1, 2));

            float mn0 = fmaxf(mx[mt * 2], tm0);
            float mn1 = fmaxf(mx[mt * 2 + 1], tm1);
            float cr0 = __expf(mx[mt * 2] - mn0);
            float cr1 = __expf(mx[mt * 2 + 1] - mn1);
            mx[mt * 2] = mn0; mx[mt * 2 + 1] = mn1;
            lsum[mt * 2] *= cr0; lsum[mt * 2 + 1] *= cr1;
#pragma unroll
            for (int nt = 0; nt < 8; nt++) {
                o[mt][nt][0] *= cr0; o[mt][nt][1] *= cr0;
                o[mt][nt][2] *= cr1; o[mt][nt][3] *= cr1;
            }
            int qrow = qA + mt * 16;
#pragma unroll
            for (int nt = 0; nt < 8; nt++) {
                float p0 = f2tf32f(__expf(s[mt][nt][0] - mn0));
                float p1 = f2tf32f(__expf(s[mt][nt][1] - mn0));
                float p2 = f2tf32f(__expf(s[mt][nt][2] - mn1));
                float p3 = f2tf32f(__expf(s[mt][nt][3] - mn1));
                lsum[mt * 2]     += p0 + p1;
                lsum[mt * 2 + 1] += p2 + p3;
                int col = nt * 8 + 2 * t;
                Ps[qrow * AP + col]           = p0;
                Ps[qrow * AP + col + 1]       = p1;
                Ps[(qrow + 8) * AP + col]     = p2;
                Ps[(qrow + 8) * AP + col + 1] = p3;
            }
        }
        __syncwarp();   // P rows are warp-private; order STS -> LDS in-warp

        // O += P V for both m-tiles, sharing V fragment loads
#pragma unroll
        for (int kc = 0; kc < 8; kc++) {
            uint32_t a[2][4];
#pragma unroll
            for (int mt = 0; mt < 2; mt++) {
                int pb_ = (qA + mt * 16) * AP + kc * 8 + t;
                a[mt][0] = __float_as_uint(Ps[pb_]);
                a[mt][1] = __float_as_uint(Ps[pb_ + 8 * AP]);
                a[mt][2] = __float_as_uint(Ps[pb_ + 4]);
                a[mt][3] = __float_as_uint(Ps[pb_ + 8 * AP + 4]);
            }
#pragma unroll
            for (int nt = 0; nt < 8; nt++) {
                int bb_ = (nt * 8 + g) * AP + kc * 8 + t;
                uint32_t b0 = __float_as_uint(Vt[bb_]);
                uint32_t b1 = __float_as_uint(Vt[bb_ + 4]);
                mma_tf32(o[0][nt], a[0][0], a[0][1], a[0][2], a[0][3], b0, b1);
                mma_tf32(o[1][nt], a[1][0], a[1][1], a[1][2], a[1][3], b0, b1);
            }
        }
        __syncwarp();   // PV reads done before next tile's P stores
    }

    // final row sums (across the 4 t-lanes) and output
#pragma unroll
    for (int i = 0; i < 4; i++) {
        lsum[i] += __shfl_xor_sync(0xffffffffu, lsum[i], 1);
        lsum[i] += __shfl_xor_sync(0xffffffffu, lsum[i], 2);
    }
#pragma unroll
    for (int mt = 0; mt < 2; mt++) {
        float inv0 = 1.f / lsum[mt * 2], inv1 = 1.f / lsum[mt * 2 + 1];
        int qrow = qA + mt * 16;
        float* out0 = AO + (size_t)(b * PS + q0 + qrow) * PD + h * 64;
        float* out1 = out0 + (size_t)8 * PD;
#pragma unroll
        for (int nt = 0; nt < 8; nt++) {
            int d = nt * 8 + 2 * t;
            *(float2*)(out0 + d) = make_float2(o[mt][nt][0] * inv0,
                                               o[mt][nt][1] * inv0);
            *(float2*)(out1 + d) = make_float2(o[mt][nt][2] * inv1,
                                               o[mt][nt][3] * inv1);
        }
    }
}

// ---------------------------------------------------------------------------
extern "C" void kernel_launch(void* const* d_in, const int* in_sizes, int n_in,
                              void* d_out, int out_size)
{
    const float* q   = (const float*)d_in[0];
    const float* k   = (const float*)d_in[1];
    const float* v   = (const float*)d_in[2];
    const float* Wq  = (const float*)d_in[3];
    const float* bq  = (const float*)d_in[4];
    const float* Wk  = (const float*)d_in[5];
    const float* bk  = (const float*)d_in[6];
    const float* Wv  = (const float*)d_in[7];
    const float* bv  = (const float*)d_in[8];
    const float* Wo  = (const float*)d_in[9];
    const float* bo  = (const float*)d_in[10];
    const int*   msk = (const int*)d_in[11];
    float* out = (float*)d_out;

    float *qh, *kh, *vh, *ao;
    cudaGetSymbolAddress((void**)&qh, g_Qh);
    cudaGetSymbolAddress((void**)&kh, g_Kh);
    cudaGetSymbolAddress((void**)&vh, g_Vh);
    cudaGetSymbolAddress((void**)&ao, g_AO);

    uint32_t *qhS, *qlS, *khS, *klS, *vhS, *vlS, *aohS, *aolS;
    uint32_t *WqhS, *WqlS, *WkhS, *WklS, *WvhS, *WvlS, *WohS, *WolS;
    cudaGetSymbolAddress((void**)&qhS,  g_qhS);
    cudaGetSymbolAddress((void**)&qlS,  g_qlS);
    cudaGetSymbolAddress((void**)&khS,  g_khS);
    cudaGetSymbolAddress((void**)&klS,  g_klS);
    cudaGetSymbolAddress((void**)&vhS,  g_vhS);
    cudaGetSymbolAddress((void**)&vlS,  g_vlS);
    cudaGetSymbolAddress((void**)&aohS, g_aohS);
    cudaGetSymbolAddress((void**)&aolS, g_aolS);
    cudaGetSymbolAddress((void**)&WqhS, g_WqhS);
    cudaGetSymbolAddress((void**)&WqlS, g_WqlS);
    cudaGetSymbolAddress((void**)&WkhS, g_WkhS);
    cudaGetSymbolAddress((void**)&WklS, g_WklS);
    cudaGetSymbolAddress((void**)&WvhS, g_WvhS);
    cudaGetSymbolAddress((void**)&WvlS, g_WvlS);
    cudaGetSymbolAddress((void**)&WohS, g_WohS);
    cudaGetSymbolAddress((void**)&WolS, g_WolS);

    const int NX4 = PM * PD / 8;   // uint4 groups per activation tensor
    const int NW4 = PD * PD / 8;   // per weight tensor

    split_kernel<<<NX4 / 256, 256>>>(q,  qhS, qlS);
    split_kernel<<<NX4 / 256, 256>>>(k,  khS, klS);
    split_kernel<<<NX4 / 256, 256>>>(v,  vhS, vlS);
    split_kernel<<<NW4 / 256, 256>>>(Wq, WqhS, WqlS);
    split_kernel<<<NW4 / 256, 256>>>(Wk, WkhS, WklS);
    split_kernel<<<NW4 / 256, 256>>>(Wv, WvhS, WvlS);
    split_kernel<<<NW4 / 256, 256>>>(Wo, WohS, WolS);

    dim3 pgrid(PD / 128, PM / 128);   // (8, 64)
    dim3 pblk(256);
    cudaFuncSetAttribute(proj2_kernel,
                         cudaFuncAttributeMaxDynamicSharedMemorySize,
                         PROJ_SMEM_BYTES);

    proj2_kernel<<<pgrid, pblk, PROJ_SMEM_BYTES>>>(qhS, qlS, WqhS, WqlS, bq, qh, 1);
    proj2_kernel<<<pgrid, pblk, PROJ_SMEM_BYTES>>>(khS, klS, WkhS, WklS, bk, kh, 1);
    proj2_kernel<<<pgrid, pblk, PROJ_SMEM_BYTES>>>(vhS, vlS, WvhS, WvlS, bv, vh, 1);

    cudaFuncSetAttribute(attn_tc_kernel,
                         cudaFuncAttributeMaxDynamicSharedMemorySize,
                         ATTN_SMEM_BYTES);
    attn_tc_kernel<<<dim3(PS / 128, PH, PB), 128, ATTN_SMEM_BYTES>>>(msk, ao);

    split_kernel<<<NX4 / 256, 256>>>(ao, aohS, aolS);
    proj2_kernel<<<pgrid, pblk, PROJ_SMEM_BYTES>>>(aohS, aolS, WohS, WolS, bo, out, 0);
}